// round 13
// baseline (speedup 1.0000x reference)
#include <cuda_runtime.h>
#include <cuda_fp16.h>
#include <math.h>
#include <stdint.h>

// ---------------------------------------------------------------------------
// Problem constants
// ---------------------------------------------------------------------------
#define BB   4
#define SS   1024
#define DD   1024
#define HH   16
#define HD   64
#define DFF  4096
#define MEMN 256
#define ROWS (BB * SS)          // 4096

#define SZ   ((size_t)ROWS * DD)        // 4M floats per slice
__device__ float g_scratch[14 * SZ];

// ---------------------------------------------------------------------------
// helpers
// ---------------------------------------------------------------------------
__device__ __forceinline__ uint32_t smem_u32(const void* p) {
    uint32_t a;
    asm("{ .reg .u64 t; cvta.to.shared.u64 t, %1; cvt.u32.u64 %0, t; }"
        : "=r"(a) : "l"(p));
    return a;
}
#define CPA16(dst, src) \
    asm volatile("cp.async.ca.shared.global [%0], [%1], 16;" :: "r"(dst), "l"(src))
#define CP_COMMIT() asm volatile("cp.async.commit_group;" ::: "memory")
#define CP_WAIT1()  asm volatile("cp.async.wait_group 1;"  ::: "memory")
#define CP_WAIT0()  asm volatile("cp.async.wait_group 0;"  ::: "memory")

__device__ __forceinline__ void round8h(float4 a, float4 b, uint4& hi) {
    __half2 h0 = __floats2half2_rn(a.x, a.y);
    __half2 h1 = __floats2half2_rn(a.z, a.w);
    __half2 h2 = __floats2half2_rn(b.x, b.y);
    __half2 h3 = __floats2half2_rn(b.z, b.w);
    hi.x = *(uint32_t*)&h0; hi.y = *(uint32_t*)&h1; hi.z = *(uint32_t*)&h2; hi.w = *(uint32_t*)&h3;
}
__device__ __forceinline__ uint32_t pack2h(float x, float y) {
    __half2 h = __floats2half2_rn(x, y);
    return *(uint32_t*)&h;
}
__device__ __forceinline__ float gelu_exact(float x) {
    return 0.5f * x * (1.0f + erff(x * 0.70710678118654752440f));
}
__device__ __forceinline__ void mma16816h(float* d, const uint32_t* a, const uint32_t* b) {
    asm volatile("mma.sync.aligned.m16n8k16.row.col.f32.f16.f16.f32 "
        "{%0,%1,%2,%3}, {%4,%5,%6,%7}, {%8,%9}, {%0,%1,%2,%3};"
        : "+f"(d[0]), "+f"(d[1]), "+f"(d[2]), "+f"(d[3])
        : "r"(a[0]), "r"(a[1]), "r"(a[2]), "r"(a[3]), "r"(b[0]), "r"(b[1]));
}
__device__ __forceinline__ void ldsm4(uint32_t* r, uint32_t addr) {
    asm volatile("ldmatrix.sync.aligned.m8n8.x4.shared.b16 {%0,%1,%2,%3}, [%4];"
        : "=r"(r[0]), "=r"(r[1]), "=r"(r[2]), "=r"(r[3]) : "r"(addr));
}
__device__ __forceinline__ void ldsm4t(uint32_t* r, uint32_t addr) {
    asm volatile("ldmatrix.sync.aligned.m8n8.x4.trans.shared.b16 {%0,%1,%2,%3}, [%4];"
        : "=r"(r[0]), "=r"(r[1]), "=r"(r[2]), "=r"(r[3]) : "r"(addr));
}

// ---------------------------------------------------------------------------
// Merged conversion kernel: 7 segments (6 weights + memory), one launch.
// ---------------------------------------------------------------------------
struct ConvArgs {
    const float* src[7];
    __half* dst[7];
    int start[8];
};
__global__ __launch_bounds__(256)
void conv_all(ConvArgs a) {
    int blk = blockIdx.x;
    int s = 0;
    #pragma unroll
    for (int k = 1; k < 7; k++) if (blk >= a.start[k]) s = k;
    int i = (blk - a.start[s]) * 2048 + threadIdx.x * 8;
    const float* in = a.src[s];
    float4 x = *(const float4*)(in + i);
    float4 y = *(const float4*)(in + i + 4);
    uint4 h;
    round8h(x, y, h);
    *(uint4*)(a.dst[s] + i) = h;
}

// ---------------------------------------------------------------------------
// Plain fp16 mma.sync GEMM (unchanged from R12 passing kernel)
// ---------------------------------------------------------------------------
#define TSTR 40
#define GASZ (128 * TSTR)
#define GBUF (2 * GASZ)
#define GBUFB (GBUF * 2)
#define GSMEM_BYTES (2 * GBUFB)   // 40960

template<int ACT, bool HASRES, bool OHALF>
__global__ __launch_bounds__(256, 2)
void mma_gemm(const __half* __restrict__ AH, const __half* __restrict__ WH,
              int K, const float* __restrict__ bias, const float* __restrict__ R,
              float* __restrict__ C, __half* __restrict__ OH, int ldc)
{
    extern __shared__ __half dsm[];
    uint32_t sb = smem_u32(dsm);

    int tid  = threadIdx.x;
    int wid  = tid >> 5, lane = tid & 31;
    int m0   = blockIdx.y * 128, n0 = blockIdx.x * 128;

    const __half* gp[4];
    uint32_t smoff[4];
    #pragma unroll
    for (int s = 0; s < 4; s++) {
        int seg = tid + s * 256;
        int arr = seg >> 9;
        int rem = seg & 511;
        int row = rem >> 2;
        int col = (rem & 3) * 8;
        const __half* base = (arr == 0) ? AH + (size_t)(m0 + row) * K
                                        : WH + (size_t)(n0 + row) * K;
        gp[s] = base + col;
        smoff[s] = (uint32_t)(arr * GASZ + row * TSTR + col) * 2;
    }

    int wm = (wid & 1) * 64;
    int wn = (wid >> 1) * 32;
    int r  = lane >> 2;
    int cq = (lane & 3) * 2;

    float acc[4][4][4];
    #pragma unroll
    for (int mt = 0; mt < 4; mt++)
        #pragma unroll
        for (int nt = 0; nt < 4; nt++)
            #pragma unroll
            for (int i = 0; i < 4; i++) acc[mt][nt][i] = 0.f;

    #pragma unroll
    for (int s = 0; s < 4; s++) CPA16(sb + smoff[s], gp[s]);
    CP_COMMIT();

    int NC = K >> 5;
    for (int c = 0; c < NC; ++c) {
        if (c + 1 < NC) {
            uint32_t boff = (uint32_t)(((c + 1) & 1) * GBUFB);
            #pragma unroll
            for (int s = 0; s < 4; s++) CPA16(sb + boff + smoff[s], gp[s] + (c + 1) * 32);
            CP_COMMIT();
            CP_WAIT1();
        } else {
            CP_WAIT0();
        }
        __syncthreads();

        {
            const __half* Ah = dsm + (c & 1) * GBUF;
            const __half* Bh = Ah + GASZ;
            #pragma unroll
            for (int kh = 0; kh < 2; kh++) {
                int cc = cq + kh * 16;
                uint32_t ah[4][4], bh[4][2];
                #pragma unroll
                for (int mt = 0; mt < 4; mt++) {
                    int rb = (wm + mt * 16 + r) * TSTR;
                    int rb8 = rb + 8 * TSTR;
                    ah[mt][0] = *(const uint32_t*)&Ah[rb + cc];
                    ah[mt][1] = *(const uint32_t*)&Ah[rb8 + cc];
                    ah[mt][2] = *(const uint32_t*)&Ah[rb + cc + 8];
                    ah[mt][3] = *(const uint32_t*)&Ah[rb8 + cc + 8];
                }
                #pragma unroll
                for (int nt = 0; nt < 4; nt++) {
                    int nb = (wn + nt * 8 + r) * TSTR;
                    bh[nt][0] = *(const uint32_t*)&Bh[nb + cc];
                    bh[nt][1] = *(const uint32_t*)&Bh[nb + cc + 8];
                }
                #pragma unroll
                for (int mt = 0; mt < 4; mt++)
                    #pragma unroll
                    for (int nt = 0; nt < 4; nt++)
                        mma16816h(acc[mt][nt], ah[mt], bh[nt]);
            }
        }
        __syncthreads();
    }

    #pragma unroll
    for (int mt = 0; mt < 4; mt++) {
        int row0 = m0 + wm + mt * 16 + r;
        #pragma unroll
        for (int nt = 0; nt < 4; nt++) {
            int coln = n0 + wn + nt * 8 + cq;
            float2 bv = *(const float2*)(bias + coln);
            float v0 = acc[mt][nt][0] + bv.x;
            float v1 = acc[mt][nt][1] + bv.y;
            float v2 = acc[mt][nt][2] + bv.x;
            float v3 = acc[mt][nt][3] + bv.y;
            if (ACT == 1) {
                v0 = gelu_exact(v0); v1 = gelu_exact(v1);
                v2 = gelu_exact(v2); v3 = gelu_exact(v3);
            }
            if (HASRES) {
                float2 r0 = *(const float2*)(R + (size_t)row0 * ldc + coln);
                float2 r1 = *(const float2*)(R + (size_t)(row0 + 8) * ldc + coln);
                v0 += r0.x; v1 += r0.y; v2 += r1.x; v3 += r1.y;
            }
            if (OHALF) {
                *(uint32_t*)(OH + (size_t)row0 * ldc + coln)       = pack2h(v0, v1);
                *(uint32_t*)(OH + (size_t)(row0 + 8) * ldc + coln) = pack2h(v2, v3);
            } else {
                *(float2*)(C + (size_t)row0 * ldc + coln)       = make_float2(v0, v1);
                *(float2*)(C + (size_t)(row0 + 8) * ldc + coln) = make_float2(v2, v3);
            }
        }
    }
}

// ---------------------------------------------------------------------------
// fp16 flash attention: cp.async double-buffered KV pipeline + ldmatrix.
// K/V stored [key][dim] stride 72. RoPE applied in-smem to K after arrival.
// ---------------------------------------------------------------------------
#define FSTR 72
#define KTILEH (64 * FSTR)          // 4608 halves per K (or V) tile
#define FBUFH  (2 * KTILEH)         // halves per buffer (K + V)
#define FBUFB  (FBUFH * 2)          // 18432 bytes per buffer
#define FSMEM_BYTES (2 * FBUFB)     // 36864

template<int CAUSAL, int ROPE>
__global__ __launch_bounds__(256, 2)
void fa_kernel(const __half* __restrict__ Q, int ldq,
               const __half* __restrict__ Kp, int ldk,
               const __half* __restrict__ Vp, int ldv,
               __half* __restrict__ OH, int ldo, int kvlen,
               const float* __restrict__ cosb, const float* __restrict__ sinb)
{
    extern __shared__ __half fsm[];
    uint32_t sb = smem_u32(fsm);

    int tid = threadIdx.x;
    int wid = tid >> 5, lane = tid & 31;
    int r   = lane >> 2;
    int cq  = (lane & 3) * 2;
    int b = blockIdx.z, h = blockIdx.y;
    int q0 = blockIdx.x * 128;
    int qrow0 = q0 + wid * 16 + r;
    int wmin  = q0 + wid * 16;
    int wmax  = wmin + 15;

    int lm  = lane & 7;
    int grp = lane >> 3;
    uint32_t kfrag0 = (uint32_t)((((grp >> 1) * 8 + lm) * FSTR + 8 * (grp & 1))) * 2;
    uint32_t vfrag0 = (uint32_t)(((8 * (grp & 1) + lm) * FSTR + (grp >> 1) * 8)) * 2;

    // tile-load mapping: one key row, 16-dim column group per thread
    int kkey = tid >> 2, kdg = (tid & 3) * 16;
    const __half* ksrc = Kp + (size_t)(b * kvlen + kkey) * ldk + h * 64 + kdg;
    const __half* vsrc = Vp + (size_t)(b * kvlen + kkey) * ldv + h * 64 + kdg;
    uint32_t kdst = sb + (uint32_t)(kkey * FSTR + kdg) * 2;
    uint32_t vdst = kdst + KTILEH * 2;

    // Q fragments (rope fused)
    uint32_t qh[4][4];
    {
        const __half* qb  = Q + (size_t)(b * SS + qrow0) * ldq + h * 64;
        const __half* qb8 = qb + (size_t)8 * ldq;
        #pragma unroll
        for (int ks = 0; ks < 4; ks++) {
            float2 f0 = __half22float2(*(const __half2*)(qb  + 16 * ks + cq));
            float2 f1 = __half22float2(*(const __half2*)(qb8 + 16 * ks + cq));
            float2 f2 = __half22float2(*(const __half2*)(qb  + 16 * ks + cq + 8));
            float2 f3 = __half22float2(*(const __half2*)(qb8 + 16 * ks + cq + 8));
            if (ROPE) {
                int i0 = (16 * ks + cq) >> 1;
                int i1 = i0 + 4;
                float c0 = cosb[qrow0 * 32 + i0],       s0 = sinb[qrow0 * 32 + i0];
                float c8 = cosb[(qrow0 + 8) * 32 + i0], s8 = sinb[(qrow0 + 8) * 32 + i0];
                float c1 = cosb[qrow0 * 32 + i1],       s1 = sinb[qrow0 * 32 + i1];
                float c9 = cosb[(qrow0 + 8) * 32 + i1], s9 = sinb[(qrow0 + 8) * 32 + i1];
                f0 = make_float2(f0.x * c0 - f0.y * s0, f0.x * s0 + f0.y * c0);
                f1 = make_float2(f1.x * c8 - f1.y * s8, f1.x * s8 + f1.y * c8);
                f2 = make_float2(f2.x * c1 - f2.y * s1, f2.x * s1 + f2.y * c1);
                f3 = make_float2(f3.x * c9 - f3.y * s9, f3.x * s9 + f3.y * c9);
            }
            qh[ks][0] = pack2h(f0.x * 0.125f, f0.y * 0.125f);
            qh[ks][1] = pack2h(f1.x * 0.125f, f1.y * 0.125f);
            qh[ks][2] = pack2h(f2.x * 0.125f, f2.y * 0.125f);
            qh[ks][3] = pack2h(f3.x * 0.125f, f3.y * 0.125f);
        }
    }

    float oacc[8][4];
    #pragma unroll
    for (int nf = 0; nf < 8; nf++)
        #pragma unroll
        for (int i = 0; i < 4; i++) oacc[nf][i] = 0.f;
    float mrun0 = -INFINITY, mrun1 = -INFINITY, l0 = 0.f, l1 = 0.f;

    int ntiles = CAUSAL ? ((q0 >> 6) + 2) : (kvlen >> 6);

    // prologue: issue tile 0 into buffer 0
    {
        CPA16(kdst,      ksrc);
        CPA16(kdst + 16, ksrc + 8);
        CPA16(vdst,      vsrc);
        CPA16(vdst + 16, vsrc + 8);
        CP_COMMIT();
    }

    for (int tile = 0; tile < ntiles; tile++) {
        int buf = tile & 1;
        uint32_t bo = (uint32_t)buf * FBUFB;
        __syncthreads();   // prior compute on buf^1 done before overwrite
        if (tile + 1 < ntiles) {
            uint32_t nbo = (uint32_t)((tile + 1) & 1) * FBUFB;
            size_t go = (size_t)(tile + 1) * 64 * ldk;
            size_t gv = (size_t)(tile + 1) * 64 * ldv;
            CPA16(kdst + nbo,      ksrc + go);
            CPA16(kdst + nbo + 16, ksrc + go + 8);
            CPA16(vdst + nbo,      vsrc + gv);
            CPA16(vdst + nbo + 16, vsrc + gv + 8);
            CP_COMMIT();
            CP_WAIT1();
        } else {
            CP_WAIT0();
        }
        __syncthreads();   // tile data valid in buf

        int t0 = tile * 64;
        if (ROPE) {
            // in-place rope on K rows (each thread transforms its own bytes)
            __half* kr = fsm + buf * FBUFH + kkey * FSTR + kdg;
            uint4 p0 = *(uint4*)kr;
            uint4 p1 = *(uint4*)(kr + 8);
            int s = t0 + kkey;
            const float* cb = cosb + s * 32 + (kdg >> 1);
            const float* sbn = sinb + s * 32 + (kdg >> 1);
            uint32_t o[8];
            #pragma unroll
            for (int j = 0; j < 4; j++) {
                float2 f = __half22float2(((const __half2*)&p0)[j]);
                float c = cb[j], sn = sbn[j];
                o[j] = pack2h(f.x * c - f.y * sn, f.x * sn + f.y * c);
            }
            #pragma unroll
            for (int j = 0; j < 4; j++) {
                float2 f = __half22float2(((const __half2*)&p1)[j]);
                float c = cb[4 + j], sn = sbn[4 + j];
                o[4 + j] = pack2h(f.x * c - f.y * sn, f.x * sn + f.y * c);
            }
            *(uint4*)kr       = *(uint4*)&o[0];
            *(uint4*)(kr + 8) = *(uint4*)&o[4];
            __syncthreads();
        }

        bool active = !CAUSAL || (t0 <= wmax);
        if (!active) continue;

        uint32_t kfb = sb + bo + kfrag0;
        uint32_t vfb = sb + bo + KTILEH * 2 + vfrag0;

        float sc[8][4];
        #pragma unroll
        for (int nf = 0; nf < 8; nf++)
            #pragma unroll
            for (int i = 0; i < 4; i++) sc[nf][i] = 0.f;

        #pragma unroll
        for (int ks = 0; ks < 4; ks++) {
            #pragma unroll
            for (int i = 0; i < 4; i++) {
                uint32_t bh[4];
                ldsm4(bh, kfb + (uint32_t)(i * 16 * FSTR + 16 * ks) * 2);
                mma16816h(sc[2 * i],     qh[ks], bh);
                mma16816h(sc[2 * i + 1], qh[ks], bh + 2);
            }
        }

        if (CAUSAL && (t0 + 63 > wmin)) {
            #pragma unroll
            for (int nf = 0; nf < 8; nf++) {
                int jb = t0 + nf * 8 + cq;
                if (jb     > qrow0)     sc[nf][0] = -INFINITY;
                if (jb + 1 > qrow0)     sc[nf][1] = -INFINITY;
                if (jb     > qrow0 + 8) sc[nf][2] = -INFINITY;
                if (jb + 1 > qrow0 + 8) sc[nf][3] = -INFINITY;
            }
        }

        float mx0 = -INFINITY, mx1 = -INFINITY;
        #pragma unroll
        for (int nf = 0; nf < 8; nf++) {
            mx0 = fmaxf(mx0, fmaxf(sc[nf][0], sc[nf][1]));
            mx1 = fmaxf(mx1, fmaxf(sc[nf][2], sc[nf][3]));
        }
        mx0 = fmaxf(mx0, __shfl_xor_sync(0xffffffffu, mx0, 1));
        mx0 = fmaxf(mx0, __shfl_xor_sync(0xffffffffu, mx0, 2));
        mx1 = fmaxf(mx1, __shfl_xor_sync(0xffffffffu, mx1, 1));
        mx1 = fmaxf(mx1, __shfl_xor_sync(0xffffffffu, mx1, 2));
        float mn0 = fmaxf(mrun0, mx0), mn1 = fmaxf(mrun1, mx1);
        float c0 = __expf(mrun0 - mn0), c1 = __expf(mrun1 - mn1);
        float s0 = 0.f, s1 = 0.f;
        #pragma unroll
        for (int nf = 0; nf < 8; nf++) {
            sc[nf][0] = __expf(sc[nf][0] - mn0);
            sc[nf][1] = __expf(sc[nf][1] - mn0);
            sc[nf][2] = __expf(sc[nf][2] - mn1);
            sc[nf][3] = __expf(sc[nf][3] - mn1);
            s0 += sc[nf][0] + sc[nf][1];
            s1 += sc[nf][2] + sc[nf][3];
        }
        s0 += __shfl_xor_sync(0xffffffffu, s0, 1);
        s0 += __shfl_xor_sync(0xffffffffu, s0, 2);
        s1 += __shfl_xor_sync(0xffffffffu, s1, 1);
        s1 += __shfl_xor_sync(0xffffffffu, s1, 2);
        l0 = l0 * c0 + s0;
        l1 = l1 * c1 + s1;
        mrun0 = mn0; mrun1 = mn1;
        #pragma unroll
        for (int nf = 0; nf < 8; nf++) {
            oacc[nf][0] *= c0; oacc[nf][1] *= c0;
            oacc[nf][2] *= c1; oacc[nf][3] *= c1;
        }

        #pragma unroll
        for (int kg = 0; kg < 4; kg++) {
            uint32_t pah[4];
            pah[0] = pack2h(sc[2 * kg][0],     sc[2 * kg][1]);
            pah[1] = pack2h(sc[2 * kg][2],     sc[2 * kg][3]);
            pah[2] = pack2h(sc[2 * kg + 1][0], sc[2 * kg + 1][1]);
            pah[3] = pack2h(sc[2 * kg + 1][2], sc[2 * kg + 1][3]);
            #pragma unroll
            for (int i = 0; i < 4; i++) {
                uint32_t bv[4];
                ldsm4t(bv, vfb + (uint32_t)(16 * kg * FSTR + i * 16) * 2);
                mma16816h(oacc[2 * i],     pah, bv);
                mma16816h(oacc[2 * i + 1], pah, bv + 2);
            }
        }
    }

    float inv0 = 1.0f / l0, inv1 = 1.0f / l1;
    size_t ob  = (size_t)(b * SS + qrow0) * ldo + h * 64;
    size_t ob8 = ob + (size_t)8 * ldo;
    #pragma unroll
    for (int nf = 0; nf < 8; nf++) {
        *(uint32_t*)(OH + ob  + nf * 8 + cq) = pack2h(oacc[nf][0] * inv0, oacc[nf][1] * inv0);
        *(uint32_t*)(OH + ob8 + nf * 8 + cq) = pack2h(oacc[nf][2] * inv1, oacc[nf][3] * inv1);
    }
}

// ---------------------------------------------------------------------------
// LayerNorm with fused fp16 output
// ---------------------------------------------------------------------------
__global__ __launch_bounds__(256)
void ln_round_kernel(const float* __restrict__ X, const float* __restrict__ gam,
                     const float* __restrict__ bet, __half* __restrict__ OH)
{
    int row = blockIdx.x;
    int t = threadIdx.x;
    int lane = t & 31, w = t >> 5;
    const float4* x4 = (const float4*)(X + (size_t)row * DD);
    float4 v = x4[t];
    float s  = v.x + v.y + v.z + v.w;
    float ss = v.x * v.x + v.y * v.y + v.z * v.z + v.w * v.w;
    #pragma unroll
    for (int o = 16; o > 0; o >>= 1) {
        s  += __shfl_xor_sync(0xffffffffu, s,  o);
        ss += __shfl_xor_sync(0xffffffffu, ss, o);
    }
    __shared__ float red[16];
    if (lane == 0) { red[w] = s; red[w + 8] = ss; }
    __syncthreads();
    float st = 0.f, sst = 0.f;
    #pragma unroll
    for (int i = 0; i < 8; i++) { st += red[i]; sst += red[i + 8]; }
    float mu   = st * (1.0f / DD);
    float var  = sst * (1.0f / DD) - mu * mu;
    float rstd = rsqrtf(var + 1e-5f);
    const float4* g4 = (const float4*)gam;
    const float4* b4 = (const float4*)bet;
    float4 gg = g4[t], bb = b4[t], o4;
    o4.x = (v.x - mu) * rstd * gg.x + bb.x;
    o4.y = (v.y - mu) * rstd * gg.y + bb.y;
    o4.z = (v.z - mu) * rstd * gg.z + bb.z;
    o4.w = (v.w - mu) * rstd * gg.w + bb.w;
    size_t off = (size_t)row * DD + t * 4;
    *(uint2*)(OH + off) = make_uint2(pack2h(o4.x, o4.y), pack2h(o4.z, o4.w));
}

// ---------------------------------------------------------------------------
// Host orchestration (stream-forked independent work)
// ---------------------------------------------------------------------------
extern "C" void kernel_launch(void* const* d_in, const int* in_sizes, int n_in,
                              void* d_out, int out_size)
{
    const float* tgt      = (const float*)d_in[0];
    const float* memory   = (const float*)d_in[1];
    const float* rope_cos = (const float*)d_in[3];
    const float* rope_sin = (const float*)d_in[4];
    const float* qkv_w    = (const float*)d_in[5];
    const float* qkv_b    = (const float*)d_in[6];
    const float* out_w    = (const float*)d_in[7];
    const float* out_b    = (const float*)d_in[8];
    const float* ca_in_w  = (const float*)d_in[9];
    const float* ca_in_b  = (const float*)d_in[10];
    const float* ca_out_w = (const float*)d_in[11];
    const float* ca_out_b = (const float*)d_in[12];
    const float* ffn_w1   = (const float*)d_in[13];
    const float* ffn_b1   = (const float*)d_in[14];
    const float* ffn_w2   = (const float*)d_in[15];
    const float* ffn_b2   = (const float*)d_in[16];
    const float* ln1_g    = (const float*)d_in[17];
    const float* ln1_b    = (const float*)d_in[18];
    const float* ln2_g    = (const float*)d_in[19];
    const float* ln2_b    = (const float*)d_in[20];
    const float* ln3_g    = (const float*)d_in[21];
    const float* ln3_b    = (const float*)d_in[22];
    float* outp = (float*)d_out;

    float* S_ = nullptr;
    cudaGetSymbolAddress((void**)&S_, g_scratch);
    float*  res = S_;                         // fp32 slice 0
    __half* hb  = (__half*)(S_ + SZ);
    __half* AH   = hb;                        // 4M halves  (attn io / ln out)
    __half* qkvh = hb + 4194304u;             // 12.58M halves (4096x3072)
    __half* caqh = qkvh;                      // reuse
    __half* ckvh = hb + 16777216u;            // 2M halves (1024x2048)
    __half* FH   = hb + 18874368u;            // 16.78M halves (4096x4096)
    __half* MH   = hb + 35651584u;            // 1M halves
    __half* Wb   = hb + 36700160u;            // 16.78M halves
    __half* w_qkv  = Wb;
    __half* w_out  = Wb + 3145728;
    __half* w_cain = Wb + 4194304;
    __half* w_caout= Wb + 7340032;
    __half* w_ffn1 = Wb + 8388608;
    __half* w_ffn2 = Wb + 12582912;

    static cudaStream_t sKV = nullptr, sLN = nullptr;
    static cudaEvent_t evStart, evConv, evKV, evLN;
    static bool init_done = false;
    if (!init_done) {
        cudaStreamCreateWithFlags(&sKV, cudaStreamNonBlocking);
        cudaStreamCreateWithFlags(&sLN, cudaStreamNonBlocking);
        cudaEventCreateWithFlags(&evStart, cudaEventDisableTiming);
        cudaEventCreateWithFlags(&evConv,  cudaEventDisableTiming);
        cudaEventCreateWithFlags(&evKV,    cudaEventDisableTiming);
        cudaEventCreateWithFlags(&evLN,    cudaEventDisableTiming);
        cudaFuncSetAttribute(mma_gemm<0, false, false>, cudaFuncAttributeMaxDynamicSharedMemorySize, GSMEM_BYTES);
        cudaFuncSetAttribute(mma_gemm<0, true,  false>, cudaFuncAttributeMaxDynamicSharedMemorySize, GSMEM_BYTES);
        cudaFuncSetAttribute(mma_gemm<0, false, true>,  cudaFuncAttributeMaxDynamicSharedMemorySize, GSMEM_BYTES);
        cudaFuncSetAttribute(mma_gemm<1, false, true>,  cudaFuncAttributeMaxDynamicSharedMemorySize, GSMEM_BYTES);
        cudaFuncSetAttribute(fa_kernel<1, 1>, cudaFuncAttributeMaxDynamicSharedMemorySize, FSMEM_BYTES);
        cudaFuncSetAttribute(fa_kernel<0, 0>, cudaFuncAttributeMaxDynamicSharedMemorySize, FSMEM_BYTES);
        init_done = true;
    }

    cudaEventRecord(evStart, 0);

    // ln1 on side stream, overlapping conv_all
    cudaStreamWaitEvent(sLN, evStart, 0);
    ln_round_kernel<<<ROWS, 256, 0, sLN>>>(tgt, ln1_g, ln1_b, AH);
    cudaEventRecord(evLN, sLN);

    // merged conversions on main stream
    {
        ConvArgs ca;
        ca.src[0] = qkv_w;    ca.dst[0] = w_qkv;
        ca.src[1] = out_w;    ca.dst[1] = w_out;
        ca.src[2] = ca_in_w;  ca.dst[2] = w_cain;
        ca.src[3] = ca_out_w; ca.dst[3] = w_caout;
        ca.src[4] = ffn_w1;   ca.dst[4] = w_ffn1;
        ca.src[5] = ffn_w2;   ca.dst[5] = w_ffn2;
        ca.src[6] = memory;   ca.dst[6] = MH;
        int blks[7] = {1536, 512, 1536, 512, 2048, 2048, 512};
        int acc = 0;
        for (int i = 0; i < 7; i++) { ca.start[i] = acc; acc += blks[i]; }
        ca.start[7] = acc;
        conv_all<<<acc, 256>>>(ca);
    }
    cudaEventRecord(evConv, 0);

    // CA KV projection on side stream (independent of self-attn block)
    cudaStreamWaitEvent(sKV, evConv, 0);
    mma_gemm<0, false, true><<<dim3(16, 8), 256, GSMEM_BYTES, sKV>>>(
        MH, w_cain + 1048576, DD, ca_in_b + 1024, nullptr, nullptr, ckvh, 2048);
    cudaEventRecord(evKV, sKV);

    // ---- self-attention block (main stream) ----
    cudaStreamWaitEvent(0, evLN, 0);
    mma_gemm<0, false, true><<<dim3(24, 32), 256, GSMEM_BYTES>>>(
        AH, w_qkv, DD, qkv_b, nullptr, nullptr, qkvh, 3072);
    fa_kernel<1, 1><<<dim3(SS / 128, HH, BB), 256, FSMEM_BYTES>>>(
        qkvh, 3072, qkvh + 1024, 3072, qkvh + 2048, 3072, AH, DD, SS,
        rope_cos, rope_sin);
    mma_gemm<0, true, false><<<dim3(8, 32), 256, GSMEM_BYTES>>>(
        AH, w_out, DD, out_b, tgt, res, nullptr, DD);

    // ---- cross-attention block ----
    ln_round_kernel<<<ROWS, 256>>>(res, ln2_g, ln2_b, AH);
    mma_gemm<0, false, true><<<dim3(8, 32), 256, GSMEM_BYTES>>>(
        AH, w_cain, DD, ca_in_b, nullptr, nullptr, caqh, DD);
    cudaStreamWaitEvent(0, evKV, 0);
    fa_kernel<0, 0><<<dim3(SS / 128, HH, BB), 256, FSMEM_BYTES>>>(
        caqh, DD, ckvh, 2048, ckvh + 1024, 2048, AH, DD, MEMN,
        rope_cos, rope_sin);
    mma_gemm<0, true, false><<<dim3(8, 32), 256, GSMEM_BYTES>>>(
        AH, w_caout, DD, ca_out_b, res, res, nullptr, DD);

    // ---- FFN block ----
    ln_round_kernel<<<ROWS, 256>>>(res, ln3_g, ln3_b, AH);
    mma_gemm<1, false, true><<<dim3(32, 32), 256, GSMEM_BYTES>>>(
        AH, w_ffn1, DD, ffn_b1, nullptr, nullptr, FH, DFF);
    mma_gemm<0, true, false><<<dim3(8, 32), 256, GSMEM_BYTES>>>(
        FH, w_ffn2, DFF, ffn_b2, res, outp, nullptr, DD);
}

// round 14
// speedup vs baseline: 1.4827x; 1.4827x over previous
#include <cuda_runtime.h>
#include <cuda_fp16.h>
#include <math.h>
#include <stdint.h>

// ---------------------------------------------------------------------------
// Problem constants
// ---------------------------------------------------------------------------
#define BB   4
#define SS   1024
#define DD   1024
#define HH   16
#define HD   64
#define DFF  4096
#define MEMN 256
#define ROWS (BB * SS)          // 4096

#define SZ   ((size_t)ROWS * DD)        // 4M floats per slice
__device__ float g_scratch[14 * SZ];

// ---------------------------------------------------------------------------
// helpers
// ---------------------------------------------------------------------------
__device__ __forceinline__ uint32_t smem_u32(const void* p) {
    uint32_t a;
    asm("{ .reg .u64 t; cvta.to.shared.u64 t, %1; cvt.u32.u64 %0, t; }"
        : "=r"(a) : "l"(p));
    return a;
}
#define CPA16(dst, src) \
    asm volatile("cp.async.ca.shared.global [%0], [%1], 16;" :: "r"(dst), "l"(src))
#define CP_COMMIT() asm volatile("cp.async.commit_group;" ::: "memory")
#define CP_WAIT1()  asm volatile("cp.async.wait_group 1;"  ::: "memory")
#define CP_WAIT0()  asm volatile("cp.async.wait_group 0;"  ::: "memory")

__device__ __forceinline__ void round8h(float4 a, float4 b, uint4& hi) {
    __half2 h0 = __floats2half2_rn(a.x, a.y);
    __half2 h1 = __floats2half2_rn(a.z, a.w);
    __half2 h2 = __floats2half2_rn(b.x, b.y);
    __half2 h3 = __floats2half2_rn(b.z, b.w);
    hi.x = *(uint32_t*)&h0; hi.y = *(uint32_t*)&h1; hi.z = *(uint32_t*)&h2; hi.w = *(uint32_t*)&h3;
}
__device__ __forceinline__ uint32_t pack2h(float x, float y) {
    __half2 h = __floats2half2_rn(x, y);
    return *(uint32_t*)&h;
}
__device__ __forceinline__ float gelu_exact(float x) {
    return 0.5f * x * (1.0f + erff(x * 0.70710678118654752440f));
}
__device__ __forceinline__ void mma16816h(float* d, const uint32_t* a, const uint32_t* b) {
    asm volatile("mma.sync.aligned.m16n8k16.row.col.f32.f16.f16.f32 "
        "{%0,%1,%2,%3}, {%4,%5,%6,%7}, {%8,%9}, {%0,%1,%2,%3};"
        : "+f"(d[0]), "+f"(d[1]), "+f"(d[2]), "+f"(d[3])
        : "r"(a[0]), "r"(a[1]), "r"(a[2]), "r"(a[3]), "r"(b[0]), "r"(b[1]));
}
__device__ __forceinline__ void ldsm4(uint32_t* r, uint32_t addr) {
    asm volatile("ldmatrix.sync.aligned.m8n8.x4.shared.b16 {%0,%1,%2,%3}, [%4];"
        : "=r"(r[0]), "=r"(r[1]), "=r"(r[2]), "=r"(r[3]) : "r"(addr));
}
__device__ __forceinline__ void ldsm4t(uint32_t* r, uint32_t addr) {
    asm volatile("ldmatrix.sync.aligned.m8n8.x4.trans.shared.b16 {%0,%1,%2,%3}, [%4];"
        : "=r"(r[0]), "=r"(r[1]), "=r"(r[2]), "=r"(r[3]) : "r"(addr));
}

// ---------------------------------------------------------------------------
// Merged conversion kernel: 7 segments (6 weights + memory), one launch.
// ---------------------------------------------------------------------------
struct ConvArgs {
    const float* src[7];
    __half* dst[7];
    int start[8];
};
__global__ __launch_bounds__(256)
void conv_all(ConvArgs a) {
    int blk = blockIdx.x;
    int s = 0;
    #pragma unroll
    for (int k = 1; k < 7; k++) if (blk >= a.start[k]) s = k;
    int i = (blk - a.start[s]) * 2048 + threadIdx.x * 8;
    const float* in = a.src[s];
    float4 x = *(const float4*)(in + i);
    float4 y = *(const float4*)(in + i + 4);
    uint4 h;
    round8h(x, y, h);
    *(uint4*)(a.dst[s] + i) = h;
}

// ---------------------------------------------------------------------------
// Plain fp16 mma.sync GEMM (unchanged from R12 passing kernel)
// ---------------------------------------------------------------------------
#define TSTR 40
#define GASZ (128 * TSTR)
#define GBUF (2 * GASZ)
#define GBUFB (GBUF * 2)
#define GSMEM_BYTES (2 * GBUFB)   // 40960

template<int ACT, bool HASRES, bool OHALF>
__global__ __launch_bounds__(256, 2)
void mma_gemm(const __half* __restrict__ AH, const __half* __restrict__ WH,
              int K, const float* __restrict__ bias, const float* __restrict__ R,
              float* __restrict__ C, __half* __restrict__ OH, int ldc)
{
    extern __shared__ __half dsm[];
    uint32_t sb = smem_u32(dsm);

    int tid  = threadIdx.x;
    int wid  = tid >> 5, lane = tid & 31;
    int m0   = blockIdx.y * 128, n0 = blockIdx.x * 128;

    const __half* gp[4];
    uint32_t smoff[4];
    #pragma unroll
    for (int s = 0; s < 4; s++) {
        int seg = tid + s * 256;
        int arr = seg >> 9;
        int rem = seg & 511;
        int row = rem >> 2;
        int col = (rem & 3) * 8;
        const __half* base = (arr == 0) ? AH + (size_t)(m0 + row) * K
                                        : WH + (size_t)(n0 + row) * K;
        gp[s] = base + col;
        smoff[s] = (uint32_t)(arr * GASZ + row * TSTR + col) * 2;
    }

    int wm = (wid & 1) * 64;
    int wn = (wid >> 1) * 32;
    int r  = lane >> 2;
    int cq = (lane & 3) * 2;

    float acc[4][4][4];
    #pragma unroll
    for (int mt = 0; mt < 4; mt++)
        #pragma unroll
        for (int nt = 0; nt < 4; nt++)
            #pragma unroll
            for (int i = 0; i < 4; i++) acc[mt][nt][i] = 0.f;

    #pragma unroll
    for (int s = 0; s < 4; s++) CPA16(sb + smoff[s], gp[s]);
    CP_COMMIT();

    int NC = K >> 5;
    for (int c = 0; c < NC; ++c) {
        if (c + 1 < NC) {
            uint32_t boff = (uint32_t)(((c + 1) & 1) * GBUFB);
            #pragma unroll
            for (int s = 0; s < 4; s++) CPA16(sb + boff + smoff[s], gp[s] + (c + 1) * 32);
            CP_COMMIT();
            CP_WAIT1();
        } else {
            CP_WAIT0();
        }
        __syncthreads();

        {
            const __half* Ah = dsm + (c & 1) * GBUF;
            const __half* Bh = Ah + GASZ;
            #pragma unroll
            for (int kh = 0; kh < 2; kh++) {
                int cc = cq + kh * 16;
                uint32_t ah[4][4], bh[4][2];
                #pragma unroll
                for (int mt = 0; mt < 4; mt++) {
                    int rb = (wm + mt * 16 + r) * TSTR;
                    int rb8 = rb + 8 * TSTR;
                    ah[mt][0] = *(const uint32_t*)&Ah[rb + cc];
                    ah[mt][1] = *(const uint32_t*)&Ah[rb8 + cc];
                    ah[mt][2] = *(const uint32_t*)&Ah[rb + cc + 8];
                    ah[mt][3] = *(const uint32_t*)&Ah[rb8 + cc + 8];
                }
                #pragma unroll
                for (int nt = 0; nt < 4; nt++) {
                    int nb = (wn + nt * 8 + r) * TSTR;
                    bh[nt][0] = *(const uint32_t*)&Bh[nb + cc];
                    bh[nt][1] = *(const uint32_t*)&Bh[nb + cc + 8];
                }
                #pragma unroll
                for (int mt = 0; mt < 4; mt++)
                    #pragma unroll
                    for (int nt = 0; nt < 4; nt++)
                        mma16816h(acc[mt][nt], ah[mt], bh[nt]);
            }
        }
        __syncthreads();
    }

    #pragma unroll
    for (int mt = 0; mt < 4; mt++) {
        int row0 = m0 + wm + mt * 16 + r;
        #pragma unroll
        for (int nt = 0; nt < 4; nt++) {
            int coln = n0 + wn + nt * 8 + cq;
            float2 bv = *(const float2*)(bias + coln);
            float v0 = acc[mt][nt][0] + bv.x;
            float v1 = acc[mt][nt][1] + bv.y;
            float v2 = acc[mt][nt][2] + bv.x;
            float v3 = acc[mt][nt][3] + bv.y;
            if (ACT == 1) {
                v0 = gelu_exact(v0); v1 = gelu_exact(v1);
                v2 = gelu_exact(v2); v3 = gelu_exact(v3);
            }
            if (HASRES) {
                float2 r0 = *(const float2*)(R + (size_t)row0 * ldc + coln);
                float2 r1 = *(const float2*)(R + (size_t)(row0 + 8) * ldc + coln);
                v0 += r0.x; v1 += r0.y; v2 += r1.x; v3 += r1.y;
            }
            if (OHALF) {
                *(uint32_t*)(OH + (size_t)row0 * ldc + coln)       = pack2h(v0, v1);
                *(uint32_t*)(OH + (size_t)(row0 + 8) * ldc + coln) = pack2h(v2, v3);
            } else {
                *(float2*)(C + (size_t)row0 * ldc + coln)       = make_float2(v0, v1);
                *(float2*)(C + (size_t)(row0 + 8) * ldc + coln) = make_float2(v2, v3);
            }
        }
    }
}

// ---------------------------------------------------------------------------
// fp16 flash attention: cp.async double-buffered KV pipeline + ldmatrix.
// K/V stored [key][dim] stride 72. RoPE applied in-smem to K after arrival.
// ---------------------------------------------------------------------------
#define FSTR 72
#define KTILEH (64 * FSTR)          // 4608 halves per K (or V) tile
#define FBUFH  (2 * KTILEH)         // halves per buffer (K + V)
#define FBUFB  (FBUFH * 2)          // 18432 bytes per buffer
#define FSMEM_BYTES (2 * FBUFB)     // 36864

template<int CAUSAL, int ROPE>
__global__ __launch_bounds__(256, 2)
void fa_kernel(const __half* __restrict__ Q, int ldq,
               const __half* __restrict__ Kp, int ldk,
               const __half* __restrict__ Vp, int ldv,
               __half* __restrict__ OH, int ldo, int kvlen,
               const float* __restrict__ cosb, const float* __restrict__ sinb)
{
    extern __shared__ __half fsm[];
    uint32_t sb = smem_u32(fsm);

    int tid = threadIdx.x;
    int wid = tid >> 5, lane = tid & 31;
    int r   = lane >> 2;
    int cq  = (lane & 3) * 2;
    int b = blockIdx.z, h = blockIdx.y;
    int q0 = blockIdx.x * 128;
    int qrow0 = q0 + wid * 16 + r;
    int wmin  = q0 + wid * 16;
    int wmax  = wmin + 15;

    int lm  = lane & 7;
    int grp = lane >> 3;
    uint32_t kfrag0 = (uint32_t)((((grp >> 1) * 8 + lm) * FSTR + 8 * (grp & 1))) * 2;
    uint32_t vfrag0 = (uint32_t)(((8 * (grp & 1) + lm) * FSTR + (grp >> 1) * 8)) * 2;

    int kkey = tid >> 2, kdg = (tid & 3) * 16;
    const __half* ksrc = Kp + (size_t)(b * kvlen + kkey) * ldk + h * 64 + kdg;
    const __half* vsrc = Vp + (size_t)(b * kvlen + kkey) * ldv + h * 64 + kdg;
    uint32_t kdst = sb + (uint32_t)(kkey * FSTR + kdg) * 2;
    uint32_t vdst = kdst + KTILEH * 2;

    uint32_t qh[4][4];
    {
        const __half* qb  = Q + (size_t)(b * SS + qrow0) * ldq + h * 64;
        const __half* qb8 = qb + (size_t)8 * ldq;
        #pragma unroll
        for (int ks = 0; ks < 4; ks++) {
            float2 f0 = __half22float2(*(const __half2*)(qb  + 16 * ks + cq));
            float2 f1 = __half22float2(*(const __half2*)(qb8 + 16 * ks + cq));
            float2 f2 = __half22float2(*(const __half2*)(qb  + 16 * ks + cq + 8));
            float2 f3 = __half22float2(*(const __half2*)(qb8 + 16 * ks + cq + 8));
            if (ROPE) {
                int i0 = (16 * ks + cq) >> 1;
                int i1 = i0 + 4;
                float c0 = cosb[qrow0 * 32 + i0],       s0 = sinb[qrow0 * 32 + i0];
                float c8 = cosb[(qrow0 + 8) * 32 + i0], s8 = sinb[(qrow0 + 8) * 32 + i0];
                float c1 = cosb[qrow0 * 32 + i1],       s1 = sinb[qrow0 * 32 + i1];
                float c9 = cosb[(qrow0 + 8) * 32 + i1], s9 = sinb[(qrow0 + 8) * 32 + i1];
                f0 = make_float2(f0.x * c0 - f0.y * s0, f0.x * s0 + f0.y * c0);
                f1 = make_float2(f1.x * c8 - f1.y * s8, f1.x * s8 + f1.y * c8);
                f2 = make_float2(f2.x * c1 - f2.y * s1, f2.x * s1 + f2.y * c1);
                f3 = make_float2(f3.x * c9 - f3.y * s9, f3.x * s9 + f3.y * c9);
            }
            qh[ks][0] = pack2h(f0.x * 0.125f, f0.y * 0.125f);
            qh[ks][1] = pack2h(f1.x * 0.125f, f1.y * 0.125f);
            qh[ks][2] = pack2h(f2.x * 0.125f, f2.y * 0.125f);
            qh[ks][3] = pack2h(f3.x * 0.125f, f3.y * 0.125f);
        }
    }

    float oacc[8][4];
    #pragma unroll
    for (int nf = 0; nf < 8; nf++)
        #pragma unroll
        for (int i = 0; i < 4; i++) oacc[nf][i] = 0.f;
    float mrun0 = -INFINITY, mrun1 = -INFINITY, l0 = 0.f, l1 = 0.f;

    int ntiles = CAUSAL ? ((q0 >> 6) + 2) : (kvlen >> 6);

    {
        CPA16(kdst,      ksrc);
        CPA16(kdst + 16, ksrc + 8);
        CPA16(vdst,      vsrc);
        CPA16(vdst + 16, vsrc + 8);
        CP_COMMIT();
    }

    for (int tile = 0; tile < ntiles; tile++) {
        int buf = tile & 1;
        uint32_t bo = (uint32_t)buf * FBUFB;
        __syncthreads();
        if (tile + 1 < ntiles) {
            uint32_t nbo = (uint32_t)((tile + 1) & 1) * FBUFB;
            size_t go = (size_t)(tile + 1) * 64 * ldk;
            size_t gv = (size_t)(tile + 1) * 64 * ldv;
            CPA16(kdst + nbo,      ksrc + go);
            CPA16(kdst + nbo + 16, ksrc + go + 8);
            CPA16(vdst + nbo,      vsrc + gv);
            CPA16(vdst + nbo + 16, vsrc + gv + 8);
            CP_COMMIT();
            CP_WAIT1();
        } else {
            CP_WAIT0();
        }
        __syncthreads();

        int t0 = tile * 64;
        if (ROPE) {
            __half* kr = fsm + buf * FBUFH + kkey * FSTR + kdg;
            uint4 p0 = *(uint4*)kr;
            uint4 p1 = *(uint4*)(kr + 8);
            int s = t0 + kkey;
            const float* cb = cosb + s * 32 + (kdg >> 1);
            const float* sbn = sinb + s * 32 + (kdg >> 1);
            uint32_t o[8];
            #pragma unroll
            for (int j = 0; j < 4; j++) {
                float2 f = __half22float2(((const __half2*)&p0)[j]);
                float c = cb[j], sn = sbn[j];
                o[j] = pack2h(f.x * c - f.y * sn, f.x * sn + f.y * c);
            }
            #pragma unroll
            for (int j = 0; j < 4; j++) {
                float2 f = __half22float2(((const __half2*)&p1)[j]);
                float c = cb[4 + j], sn = sbn[4 + j];
                o[4 + j] = pack2h(f.x * c - f.y * sn, f.x * sn + f.y * c);
            }
            *(uint4*)kr       = *(uint4*)&o[0];
            *(uint4*)(kr + 8) = *(uint4*)&o[4];
            __syncthreads();
        }

        bool active = !CAUSAL || (t0 <= wmax);
        if (!active) continue;

        uint32_t kfb = sb + bo + kfrag0;
        uint32_t vfb = sb + bo + KTILEH * 2 + vfrag0;

        float sc[8][4];
        #pragma unroll
        for (int nf = 0; nf < 8; nf++)
            #pragma unroll
            for (int i = 0; i < 4; i++) sc[nf][i] = 0.f;

        #pragma unroll
        for (int ks = 0; ks < 4; ks++) {
            #pragma unroll
            for (int i = 0; i < 4; i++) {
                uint32_t bh[4];
                ldsm4(bh, kfb + (uint32_t)(i * 16 * FSTR + 16 * ks) * 2);
                mma16816h(sc[2 * i],     qh[ks], bh);
                mma16816h(sc[2 * i + 1], qh[ks], bh + 2);
            }
        }

        if (CAUSAL && (t0 + 63 > wmin)) {
            #pragma unroll
            for (int nf = 0; nf < 8; nf++) {
                int jb = t0 + nf * 8 + cq;
                if (jb     > qrow0)     sc[nf][0] = -INFINITY;
                if (jb + 1 > qrow0)     sc[nf][1] = -INFINITY;
                if (jb     > qrow0 + 8) sc[nf][2] = -INFINITY;
                if (jb + 1 > qrow0 + 8) sc[nf][3] = -INFINITY;
            }
        }

        float mx0 = -INFINITY, mx1 = -INFINITY;
        #pragma unroll
        for (int nf = 0; nf < 8; nf++) {
            mx0 = fmaxf(mx0, fmaxf(sc[nf][0], sc[nf][1]));
            mx1 = fmaxf(mx1, fmaxf(sc[nf][2], sc[nf][3]));
        }
        mx0 = fmaxf(mx0, __shfl_xor_sync(0xffffffffu, mx0, 1));
        mx0 = fmaxf(mx0, __shfl_xor_sync(0xffffffffu, mx0, 2));
        mx1 = fmaxf(mx1, __shfl_xor_sync(0xffffffffu, mx1, 1));
        mx1 = fmaxf(mx1, __shfl_xor_sync(0xffffffffu, mx1, 2));
        float mn0 = fmaxf(mrun0, mx0), mn1 = fmaxf(mrun1, mx1);
        float c0 = __expf(mrun0 - mn0), c1 = __expf(mrun1 - mn1);
        float s0 = 0.f, s1 = 0.f;
        #pragma unroll
        for (int nf = 0; nf < 8; nf++) {
            sc[nf][0] = __expf(sc[nf][0] - mn0);
            sc[nf][1] = __expf(sc[nf][1] - mn0);
            sc[nf][2] = __expf(sc[nf][2] - mn1);
            sc[nf][3] = __expf(sc[nf][3] - mn1);
            s0 += sc[nf][0] + sc[nf][1];
            s1 += sc[nf][2] + sc[nf][3];
        }
        s0 += __shfl_xor_sync(0xffffffffu, s0, 1);
        s0 += __shfl_xor_sync(0xffffffffu, s0, 2);
        s1 += __shfl_xor_sync(0xffffffffu, s1, 1);
        s1 += __shfl_xor_sync(0xffffffffu, s1, 2);
        l0 = l0 * c0 + s0;
        l1 = l1 * c1 + s1;
        mrun0 = mn0; mrun1 = mn1;
        #pragma unroll
        for (int nf = 0; nf < 8; nf++) {
            oacc[nf][0] *= c0; oacc[nf][1] *= c0;
            oacc[nf][2] *= c1; oacc[nf][3] *= c1;
        }

        #pragma unroll
        for (int kg = 0; kg < 4; kg++) {
            uint32_t pah[4];
            pah[0] = pack2h(sc[2 * kg][0],     sc[2 * kg][1]);
            pah[1] = pack2h(sc[2 * kg][2],     sc[2 * kg][3]);
            pah[2] = pack2h(sc[2 * kg + 1][0], sc[2 * kg + 1][1]);
            pah[3] = pack2h(sc[2 * kg + 1][2], sc[2 * kg + 1][3]);
            #pragma unroll
            for (int i = 0; i < 4; i++) {
                uint32_t bv[4];
                ldsm4t(bv, vfb + (uint32_t)(16 * kg * FSTR + i * 16) * 2);
                mma16816h(oacc[2 * i],     pah, bv);
                mma16816h(oacc[2 * i + 1], pah, bv + 2);
            }
        }
    }

    float inv0 = 1.0f / l0, inv1 = 1.0f / l1;
    size_t ob  = (size_t)(b * SS + qrow0) * ldo + h * 64;
    size_t ob8 = ob + (size_t)8 * ldo;
    #pragma unroll
    for (int nf = 0; nf < 8; nf++) {
        *(uint32_t*)(OH + ob  + nf * 8 + cq) = pack2h(oacc[nf][0] * inv0, oacc[nf][1] * inv0);
        *(uint32_t*)(OH + ob8 + nf * 8 + cq) = pack2h(oacc[nf][2] * inv1, oacc[nf][3] * inv1);
    }
}

// ---------------------------------------------------------------------------
// LayerNorm with fused fp16 output
// ---------------------------------------------------------------------------
__global__ __launch_bounds__(256)
void ln_round_kernel(const float* __restrict__ X, const float* __restrict__ gam,
                     const float* __restrict__ bet, __half* __restrict__ OH)
{
    int row = blockIdx.x;
    int t = threadIdx.x;
    int lane = t & 31, w = t >> 5;
    const float4* x4 = (const float4*)(X + (size_t)row * DD);
    float4 v = x4[t];
    float s  = v.x + v.y + v.z + v.w;
    float ss = v.x * v.x + v.y * v.y + v.z * v.z + v.w * v.w;
    #pragma unroll
    for (int o = 16; o > 0; o >>= 1) {
        s  += __shfl_xor_sync(0xffffffffu, s,  o);
        ss += __shfl_xor_sync(0xffffffffu, ss, o);
    }
    __shared__ float red[16];
    if (lane == 0) { red[w] = s; red[w + 8] = ss; }
    __syncthreads();
    float st = 0.f, sst = 0.f;
    #pragma unroll
    for (int i = 0; i < 8; i++) { st += red[i]; sst += red[i + 8]; }
    float mu   = st * (1.0f / DD);
    float var  = sst * (1.0f / DD) - mu * mu;
    float rstd = rsqrtf(var + 1e-5f);
    const float4* g4 = (const float4*)gam;
    const float4* b4 = (const float4*)bet;
    float4 gg = g4[t], bb = b4[t], o4;
    o4.x = (v.x - mu) * rstd * gg.x + bb.x;
    o4.y = (v.y - mu) * rstd * gg.y + bb.y;
    o4.z = (v.z - mu) * rstd * gg.z + bb.z;
    o4.w = (v.w - mu) * rstd * gg.w + bb.w;
    size_t off = (size_t)row * DD + t * 4;
    *(uint2*)(OH + off) = make_uint2(pack2h(o4.x, o4.y), pack2h(o4.z, o4.w));
}

// ---------------------------------------------------------------------------
// Host orchestration (single stream, R12 ordering)
// ---------------------------------------------------------------------------
extern "C" void kernel_launch(void* const* d_in, const int* in_sizes, int n_in,
                              void* d_out, int out_size)
{
    const float* tgt      = (const float*)d_in[0];
    const float* memory   = (const float*)d_in[1];
    const float* rope_cos = (const float*)d_in[3];
    const float* rope_sin = (const float*)d_in[4];
    const float* qkv_w    = (const float*)d_in[5];
    const float* qkv_b    = (const float*)d_in[6];
    const float* out_w    = (const float*)d_in[7];
    const float* out_b    = (const float*)d_in[8];
    const float* ca_in_w  = (const float*)d_in[9];
    const float* ca_in_b  = (const float*)d_in[10];
    const float* ca_out_w = (const float*)d_in[11];
    const float* ca_out_b = (const float*)d_in[12];
    const float* ffn_w1   = (const float*)d_in[13];
    const float* ffn_b1   = (const float*)d_in[14];
    const float* ffn_w2   = (const float*)d_in[15];
    const float* ffn_b2   = (const float*)d_in[16];
    const float* ln1_g    = (const float*)d_in[17];
    const float* ln1_b    = (const float*)d_in[18];
    const float* ln2_g    = (const float*)d_in[19];
    const float* ln2_b    = (const float*)d_in[20];
    const float* ln3_g    = (const float*)d_in[21];
    const float* ln3_b    = (const float*)d_in[22];
    float* outp = (float*)d_out;

    float* S_ = nullptr;
    cudaGetSymbolAddress((void**)&S_, g_scratch);
    float*  res = S_;                         // fp32 slice 0
    __half* hb  = (__half*)(S_ + SZ);
    __half* AH   = hb;                        // 4M halves
    __half* qkvh = hb + 4194304u;             // 4096x3072
    __half* caqh = qkvh;                      // reuse
    __half* ckvh = hb + 16777216u;            // 1024x2048
    __half* FH   = hb + 18874368u;            // 4096x4096
    __half* MH   = hb + 35651584u;            // 1M halves
    __half* Wb   = hb + 36700160u;
    __half* w_qkv  = Wb;
    __half* w_out  = Wb + 3145728;
    __half* w_cain = Wb + 4194304;
    __half* w_caout= Wb + 7340032;
    __half* w_ffn1 = Wb + 8388608;
    __half* w_ffn2 = Wb + 12582912;

    static bool attr_done = false;
    if (!attr_done) {
        cudaFuncSetAttribute(mma_gemm<0, false, false>, cudaFuncAttributeMaxDynamicSharedMemorySize, GSMEM_BYTES);
        cudaFuncSetAttribute(mma_gemm<0, true,  false>, cudaFuncAttributeMaxDynamicSharedMemorySize, GSMEM_BYTES);
        cudaFuncSetAttribute(mma_gemm<0, false, true>,  cudaFuncAttributeMaxDynamicSharedMemorySize, GSMEM_BYTES);
        cudaFuncSetAttribute(mma_gemm<1, false, true>,  cudaFuncAttributeMaxDynamicSharedMemorySize, GSMEM_BYTES);
        cudaFuncSetAttribute(fa_kernel<1, 1>, cudaFuncAttributeMaxDynamicSharedMemorySize, FSMEM_BYTES);
        cudaFuncSetAttribute(fa_kernel<0, 0>, cudaFuncAttributeMaxDynamicSharedMemorySize, FSMEM_BYTES);
        attr_done = true;
    }

    // ---- merged conversions: 6 weights + memory, one launch ----
    {
        ConvArgs ca;
        ca.src[0] = qkv_w;    ca.dst[0] = w_qkv;
        ca.src[1] = out_w;    ca.dst[1] = w_out;
        ca.src[2] = ca_in_w;  ca.dst[2] = w_cain;
        ca.src[3] = ca_out_w; ca.dst[3] = w_caout;
        ca.src[4] = ffn_w1;   ca.dst[4] = w_ffn1;
        ca.src[5] = ffn_w2;   ca.dst[5] = w_ffn2;
        ca.src[6] = memory;   ca.dst[6] = MH;
        int blks[7] = {1536, 512, 1536, 512, 2048, 2048, 512};
        int acc = 0;
        for (int i = 0; i < 7; i++) { ca.start[i] = acc; acc += blks[i]; }
        ca.start[7] = acc;
        conv_all<<<acc, 256>>>(ca);
    }

    // ---- self-attention block ----
    ln_round_kernel<<<ROWS, 256>>>(tgt, ln1_g, ln1_b, AH);
    mma_gemm<0, false, true><<<dim3(24, 32), 256, GSMEM_BYTES>>>(
        AH, w_qkv, DD, qkv_b, nullptr, nullptr, qkvh, 3072);
    fa_kernel<1, 1><<<dim3(SS / 128, HH, BB), 256, FSMEM_BYTES>>>(
        qkvh, 3072, qkvh + 1024, 3072, qkvh + 2048, 3072, AH, DD, SS,
        rope_cos, rope_sin);
    mma_gemm<0, true, false><<<dim3(8, 32), 256, GSMEM_BYTES>>>(
        AH, w_out, DD, out_b, tgt, res, nullptr, DD);

    // ---- cross-attention block ----
    ln_round_kernel<<<ROWS, 256>>>(res, ln2_g, ln2_b, AH);
    mma_gemm<0, false, true><<<dim3(8, 32), 256, GSMEM_BYTES>>>(
        AH, w_cain, DD, ca_in_b, nullptr, nullptr, caqh, DD);
    mma_gemm<0, false, true><<<dim3(16, 8), 256, GSMEM_BYTES>>>(
        MH, w_cain + 1048576, DD, ca_in_b + 1024, nullptr, nullptr, ckvh, 2048);
    fa_kernel<0, 0><<<dim3(SS / 128, HH, BB), 256, FSMEM_BYTES>>>(
        caqh, DD, ckvh, 2048, ckvh + 1024, 2048, AH, DD, MEMN,
        rope_cos, rope_sin);
    mma_gemm<0, true, false><<<dim3(8, 32), 256, GSMEM_BYTES>>>(
        AH, w_caout, DD, ca_out_b, res, res, nullptr, DD);

    // ---- FFN block ----
    ln_round_kernel<<<ROWS, 256>>>(res, ln3_g, ln3_b, AH);
    mma_gemm<1, false, true><<<dim3(32, 32), 256, GSMEM_BYTES>>>(
        AH, w_ffn1, DD, ffn_b1, nullptr, nullptr, FH, DFF);
    mma_gemm<0, true, false><<<dim3(8, 32), 256, GSMEM_BYTES>>>(
        FH, w_ffn2, DFF, ffn_b2, res, outp, nullptr, DD);
}

// round 15
// speedup vs baseline: 1.7092x; 1.1527x over previous
#include <cuda_runtime.h>
#include <cuda_fp16.h>
#include <math.h>
#include <stdint.h>

// ---------------------------------------------------------------------------
// Problem constants
// ---------------------------------------------------------------------------
#define BB   4
#define SS   1024
#define DD   1024
#define HH   16
#define HD   64
#define DFF  4096
#define MEMN 256
#define ROWS (BB * SS)          // 4096

#define SZ   ((size_t)ROWS * DD)        // 4M floats per slice
__device__ float g_scratch[14 * SZ];

#define LOG2E 1.44269504088896f

// ---------------------------------------------------------------------------
// helpers
// ---------------------------------------------------------------------------
__device__ __forceinline__ uint32_t smem_u32(const void* p) {
    uint32_t a;
    asm("{ .reg .u64 t; cvta.to.shared.u64 t, %1; cvt.u32.u64 %0, t; }"
        : "=r"(a) : "l"(p));
    return a;
}
#define CPA16(dst, src) \
    asm volatile("cp.async.ca.shared.global [%0], [%1], 16;" :: "r"(dst), "l"(src))
#define CP_COMMIT() asm volatile("cp.async.commit_group;" ::: "memory")
#define CP_WAIT1()  asm volatile("cp.async.wait_group 1;"  ::: "memory")
#define CP_WAIT0()  asm volatile("cp.async.wait_group 0;"  ::: "memory")

__device__ __forceinline__ void round8h(float4 a, float4 b, uint4& hi) {
    __half2 h0 = __floats2half2_rn(a.x, a.y);
    __half2 h1 = __floats2half2_rn(a.z, a.w);
    __half2 h2 = __floats2half2_rn(b.x, b.y);
    __half2 h3 = __floats2half2_rn(b.z, b.w);
    hi.x = *(uint32_t*)&h0; hi.y = *(uint32_t*)&h1; hi.z = *(uint32_t*)&h2; hi.w = *(uint32_t*)&h3;
}
__device__ __forceinline__ uint32_t pack2h(float x, float y) {
    __half2 h = __floats2half2_rn(x, y);
    return *(uint32_t*)&h;
}
__device__ __forceinline__ float gelu_exact(float x) {
    return 0.5f * x * (1.0f + erff(x * 0.70710678118654752440f));
}
__device__ __forceinline__ void mma16816h(float* d, const uint32_t* a, const uint32_t* b) {
    asm volatile("mma.sync.aligned.m16n8k16.row.col.f32.f16.f16.f32 "
        "{%0,%1,%2,%3}, {%4,%5,%6,%7}, {%8,%9}, {%0,%1,%2,%3};"
        : "+f"(d[0]), "+f"(d[1]), "+f"(d[2]), "+f"(d[3])
        : "r"(a[0]), "r"(a[1]), "r"(a[2]), "r"(a[3]), "r"(b[0]), "r"(b[1]));
}
__device__ __forceinline__ void ldsm4(uint32_t* r, uint32_t addr) {
    asm volatile("ldmatrix.sync.aligned.m8n8.x4.shared.b16 {%0,%1,%2,%3}, [%4];"
        : "=r"(r[0]), "=r"(r[1]), "=r"(r[2]), "=r"(r[3]) : "r"(addr));
}
__device__ __forceinline__ void ldsm4t(uint32_t* r, uint32_t addr) {
    asm volatile("ldmatrix.sync.aligned.m8n8.x4.trans.shared.b16 {%0,%1,%2,%3}, [%4];"
        : "=r"(r[0]), "=r"(r[1]), "=r"(r[2]), "=r"(r[3]) : "r"(addr));
}

// ---------------------------------------------------------------------------
// Merged conversion kernel: 7 segments (6 weights + memory), one launch.
// ---------------------------------------------------------------------------
struct ConvArgs {
    const float* src[7];
    __half* dst[7];
    int start[8];
};
__global__ __launch_bounds__(256)
void conv_all(ConvArgs a) {
    int blk = blockIdx.x;
    int s = 0;
    #pragma unroll
    for (int k = 1; k < 7; k++) if (blk >= a.start[k]) s = k;
    int i = (blk - a.start[s]) * 2048 + threadIdx.x * 8;
    const float* in = a.src[s];
    float4 x = *(const float4*)(in + i);
    float4 y = *(const float4*)(in + i + 4);
    uint4 h;
    round8h(x, y, h);
    *(uint4*)(a.dst[s] + i) = h;
}

// ---------------------------------------------------------------------------
// fp16 mma.sync GEMM with ldmatrix fragment loads.
// C = A@W^T + bias (+gelu) (+residual) (+rope on q/k sections when ROPEE).
// BM=BN=128, BK=32, 256 threads, cp.async double-buffered, 2 CTAs/SM.
// ---------------------------------------------------------------------------
#define TSTR 40
#define GASZ (128 * TSTR)
#define GBUF (2 * GASZ)
#define GBUFB (GBUF * 2)
#define GSMEM_BYTES (2 * GBUFB)   // 40960

template<int ACT, bool HASRES, bool OHALF, int ROPEE>
__global__ __launch_bounds__(256, 2)
void mma_gemm(const __half* __restrict__ AH, const __half* __restrict__ WH,
              int K, const float* __restrict__ bias, const float* __restrict__ R,
              float* __restrict__ C, __half* __restrict__ OH, int ldc,
              const float* __restrict__ cosb, const float* __restrict__ sinb)
{
    extern __shared__ __half dsm[];
    uint32_t sb = smem_u32(dsm);

    int tid  = threadIdx.x;
    int wid  = tid >> 5, lane = tid & 31;
    int m0   = blockIdx.y * 128, n0 = blockIdx.x * 128;

    const __half* gp[4];
    uint32_t smoff[4];
    #pragma unroll
    for (int s = 0; s < 4; s++) {
        int seg = tid + s * 256;
        int arr = seg >> 9;
        int rem = seg & 511;
        int row = rem >> 2;
        int col = (rem & 3) * 8;
        const __half* base = (arr == 0) ? AH + (size_t)(m0 + row) * K
                                        : WH + (size_t)(n0 + row) * K;
        gp[s] = base + col;
        smoff[s] = (uint32_t)(arr * GASZ + row * TSTR + col) * 2;
    }

    int wm = (wid & 1) * 64;
    int wn = (wid >> 1) * 32;
    int r  = lane >> 2;
    int cq = (lane & 3) * 2;
    int lm  = lane & 7;
    int grp = lane >> 3;
    // ldmatrix per-lane offsets (bytes)
    uint32_t aoff = (uint32_t)((((grp & 1) * 8 + lm) * TSTR + (grp >> 1) * 8)) * 2;
    uint32_t boff = (uint32_t)((((grp >> 1) * 8 + lm) * TSTR + (grp & 1) * 8)) * 2;

    float acc[4][4][4];
    #pragma unroll
    for (int mt = 0; mt < 4; mt++)
        #pragma unroll
        for (int nt = 0; nt < 4; nt++)
            #pragma unroll
            for (int i = 0; i < 4; i++) acc[mt][nt][i] = 0.f;

    #pragma unroll
    for (int s = 0; s < 4; s++) CPA16(sb + smoff[s], gp[s]);
    CP_COMMIT();

    int NC = K >> 5;
    for (int c = 0; c < NC; ++c) {
        if (c + 1 < NC) {
            uint32_t bfo = (uint32_t)(((c + 1) & 1) * GBUFB);
            #pragma unroll
            for (int s = 0; s < 4; s++) CPA16(sb + bfo + smoff[s], gp[s] + (c + 1) * 32);
            CP_COMMIT();
            CP_WAIT1();
        } else {
            CP_WAIT0();
        }
        __syncthreads();

        {
            uint32_t ab = sb + (c & 1) * GBUFB;
            uint32_t bb = ab + GASZ * 2;
            #pragma unroll
            for (int kh = 0; kh < 2; kh++) {
                uint32_t kofs = (uint32_t)(kh * 16) * 2;
                uint32_t ah[4][4], bh[4][2];
                #pragma unroll
                for (int mt = 0; mt < 4; mt++)
                    ldsm4(ah[mt], ab + aoff + kofs +
                          (uint32_t)((wm + mt * 16) * TSTR) * 2);
                #pragma unroll
                for (int ntp = 0; ntp < 2; ntp++) {
                    uint32_t bregs[4];
                    ldsm4(bregs, bb + boff + kofs +
                          (uint32_t)((wn + ntp * 16) * TSTR) * 2);
                    bh[2 * ntp][0]     = bregs[0];
                    bh[2 * ntp][1]     = bregs[1];
                    bh[2 * ntp + 1][0] = bregs[2];
                    bh[2 * ntp + 1][1] = bregs[3];
                }
                #pragma unroll
                for (int mt = 0; mt < 4; mt++)
                    #pragma unroll
                    for (int nt = 0; nt < 4; nt++)
                        mma16816h(acc[mt][nt], ah[mt], bh[nt]);
            }
        }
        __syncthreads();
    }

    #pragma unroll
    for (int mt = 0; mt < 4; mt++) {
        int row0 = m0 + wm + mt * 16 + r;
        #pragma unroll
        for (int nt = 0; nt < 4; nt++) {
            int coln = n0 + wn + nt * 8 + cq;
            float2 bv = *(const float2*)(bias + coln);
            float v0 = acc[mt][nt][0] + bv.x;
            float v1 = acc[mt][nt][1] + bv.y;
            float v2 = acc[mt][nt][2] + bv.x;
            float v3 = acc[mt][nt][3] + bv.y;
            if (ACT == 1) {
                v0 = gelu_exact(v0); v1 = gelu_exact(v1);
                v2 = gelu_exact(v2); v3 = gelu_exact(v3);
            }
            if (ROPEE) {
                // rope on q (cols 0..1023) and k (1024..2047) sections
                if ((coln >> 10) < 2) {
                    int i  = (coln & 63) >> 1;
                    int s0 = row0 & (SS - 1);
                    float c0r = cosb[s0 * 32 + i],       s0r = sinb[s0 * 32 + i];
                    float c8r = cosb[(s0 + 8) * 32 + i], s8r = sinb[(s0 + 8) * 32 + i];
                    float t0 = v0 * c0r - v1 * s0r, t1 = v0 * s0r + v1 * c0r;
                    float t2 = v2 * c8r - v3 * s8r, t3 = v2 * s8r + v3 * c8r;
                    v0 = t0; v1 = t1; v2 = t2; v3 = t3;
                }
            }
            if (HASRES) {
                float2 r0 = *(const float2*)(R + (size_t)row0 * ldc + coln);
                float2 r1 = *(const float2*)(R + (size_t)(row0 + 8) * ldc + coln);
                v0 += r0.x; v1 += r0.y; v2 += r1.x; v3 += r1.y;
            }
            if (OHALF) {
                *(uint32_t*)(OH + (size_t)row0 * ldc + coln)       = pack2h(v0, v1);
                *(uint32_t*)(OH + (size_t)(row0 + 8) * ldc + coln) = pack2h(v2, v3);
            } else {
                *(float2*)(C + (size_t)row0 * ldc + coln)       = make_float2(v0, v1);
                *(float2*)(C + (size_t)(row0 + 8) * ldc + coln) = make_float2(v2, v3);
            }
        }
    }
}

// ---------------------------------------------------------------------------
// fp16 flash attention: cp.async double-buffered KV + ldmatrix, exp2 softmax.
// RoPE already applied upstream (GEMM epilogue). K/V [key][dim] stride 72.
// ---------------------------------------------------------------------------
#define FSTR 72
#define KTILEH (64 * FSTR)
#define FBUFH  (2 * KTILEH)
#define FBUFB  (FBUFH * 2)
#define FSMEM_BYTES (2 * FBUFB)     // 36864

template<int CAUSAL>
__global__ __launch_bounds__(256, 2)
void fa_kernel(const __half* __restrict__ Q, int ldq,
               const __half* __restrict__ Kp, int ldk,
               const __half* __restrict__ Vp, int ldv,
               __half* __restrict__ OH, int ldo, int kvlen)
{
    extern __shared__ __half fsm[];
    uint32_t sb = smem_u32(fsm);

    int tid = threadIdx.x;
    int wid = tid >> 5, lane = tid & 31;
    int r   = lane >> 2;
    int cq  = (lane & 3) * 2;
    int b = blockIdx.z, h = blockIdx.y;
    int q0 = blockIdx.x * 128;
    int qrow0 = q0 + wid * 16 + r;
    int wmin  = q0 + wid * 16;
    int wmax  = wmin + 15;

    int lm  = lane & 7;
    int grp = lane >> 3;
    uint32_t kfrag0 = (uint32_t)((((grp >> 1) * 8 + lm) * FSTR + 8 * (grp & 1))) * 2;
    uint32_t vfrag0 = (uint32_t)(((8 * (grp & 1) + lm) * FSTR + (grp >> 1) * 8)) * 2;

    int kkey = tid >> 2, kdg = (tid & 3) * 16;
    const __half* ksrc = Kp + (size_t)(b * kvlen + kkey) * ldk + h * 64 + kdg;
    const __half* vsrc = Vp + (size_t)(b * kvlen + kkey) * ldv + h * 64 + kdg;
    uint32_t kdst = sb + (uint32_t)(kkey * FSTR + kdg) * 2;
    uint32_t vdst = kdst + KTILEH * 2;

    // Q fragments, scale = 1/8 * log2e (exp2 softmax)
    uint32_t qh[4][4];
    {
        const float qs = 0.125f * LOG2E;
        const __half* qb  = Q + (size_t)(b * SS + qrow0) * ldq + h * 64;
        const __half* qb8 = qb + (size_t)8 * ldq;
        #pragma unroll
        for (int ks = 0; ks < 4; ks++) {
            float2 f0 = __half22float2(*(const __half2*)(qb  + 16 * ks + cq));
            float2 f1 = __half22float2(*(const __half2*)(qb8 + 16 * ks + cq));
            float2 f2 = __half22float2(*(const __half2*)(qb  + 16 * ks + cq + 8));
            float2 f3 = __half22float2(*(const __half2*)(qb8 + 16 * ks + cq + 8));
            qh[ks][0] = pack2h(f0.x * qs, f0.y * qs);
            qh[ks][1] = pack2h(f1.x * qs, f1.y * qs);
            qh[ks][2] = pack2h(f2.x * qs, f2.y * qs);
            qh[ks][3] = pack2h(f3.x * qs, f3.y * qs);
        }
    }

    float oacc[8][4];
    #pragma unroll
    for (int nf = 0; nf < 8; nf++)
        #pragma unroll
        for (int i = 0; i < 4; i++) oacc[nf][i] = 0.f;
    float mrun0 = -INFINITY, mrun1 = -INFINITY, l0 = 0.f, l1 = 0.f;

    int ntiles = CAUSAL ? ((q0 >> 6) + 2) : (kvlen >> 6);

    {
        CPA16(kdst,      ksrc);
        CPA16(kdst + 16, ksrc + 8);
        CPA16(vdst,      vsrc);
        CPA16(vdst + 16, vsrc + 8);
        CP_COMMIT();
    }

    for (int tile = 0; tile < ntiles; tile++) {
        uint32_t bo = (uint32_t)(tile & 1) * FBUFB;
        __syncthreads();
        if (tile + 1 < ntiles) {
            uint32_t nbo = (uint32_t)((tile + 1) & 1) * FBUFB;
            size_t go = (size_t)(tile + 1) * 64 * ldk;
            size_t gv = (size_t)(tile + 1) * 64 * ldv;
            CPA16(kdst + nbo,      ksrc + go);
            CPA16(kdst + nbo + 16, ksrc + go + 8);
            CPA16(vdst + nbo,      vsrc + gv);
            CPA16(vdst + nbo + 16, vsrc + gv + 8);
            CP_COMMIT();
            CP_WAIT1();
        } else {
            CP_WAIT0();
        }
        __syncthreads();

        int t0 = tile * 64;
        bool active = !CAUSAL || (t0 <= wmax);
        if (!active) continue;

        uint32_t kfb = sb + bo + kfrag0;
        uint32_t vfb = sb + bo + KTILEH * 2 + vfrag0;

        float sc[8][4];
        #pragma unroll
        for (int nf = 0; nf < 8; nf++)
            #pragma unroll
            for (int i = 0; i < 4; i++) sc[nf][i] = 0.f;

        #pragma unroll
        for (int ks = 0; ks < 4; ks++) {
            #pragma unroll
            for (int i = 0; i < 4; i++) {
                uint32_t bh[4];
                ldsm4(bh, kfb + (uint32_t)(i * 16 * FSTR + 16 * ks) * 2);
                mma16816h(sc[2 * i],     qh[ks], bh);
                mma16816h(sc[2 * i + 1], qh[ks], bh + 2);
            }
        }

        if (CAUSAL && (t0 + 63 > wmin)) {
            #pragma unroll
            for (int nf = 0; nf < 8; nf++) {
                int jb = t0 + nf * 8 + cq;
                if (jb     > qrow0)     sc[nf][0] = -INFINITY;
                if (jb + 1 > qrow0)     sc[nf][1] = -INFINITY;
                if (jb     > qrow0 + 8) sc[nf][2] = -INFINITY;
                if (jb + 1 > qrow0 + 8) sc[nf][3] = -INFINITY;
            }
        }

        float mx0 = -INFINITY, mx1 = -INFINITY;
        #pragma unroll
        for (int nf = 0; nf < 8; nf++) {
            mx0 = fmaxf(mx0, fmaxf(sc[nf][0], sc[nf][1]));
            mx1 = fmaxf(mx1, fmaxf(sc[nf][2], sc[nf][3]));
        }
        mx0 = fmaxf(mx0, __shfl_xor_sync(0xffffffffu, mx0, 1));
        mx0 = fmaxf(mx0, __shfl_xor_sync(0xffffffffu, mx0, 2));
        mx1 = fmaxf(mx1, __shfl_xor_sync(0xffffffffu, mx1, 1));
        mx1 = fmaxf(mx1, __shfl_xor_sync(0xffffffffu, mx1, 2));
        float mn0 = fmaxf(mrun0, mx0), mn1 = fmaxf(mrun1, mx1);
        float c0 = exp2f(mrun0 - mn0), c1 = exp2f(mrun1 - mn1);
        float s0 = 0.f, s1 = 0.f;
        #pragma unroll
        for (int nf = 0; nf < 8; nf++) {
            sc[nf][0] = exp2f(sc[nf][0] - mn0);
            sc[nf][1] = exp2f(sc[nf][1] - mn0);
            sc[nf][2] = exp2f(sc[nf][2] - mn1);
            sc[nf][3] = exp2f(sc[nf][3] - mn1);
            s0 += sc[nf][0] + sc[nf][1];
            s1 += sc[nf][2] + sc[nf][3];
        }
        s0 += __shfl_xor_sync(0xffffffffu, s0, 1);
        s0 += __shfl_xor_sync(0xffffffffu, s0, 2);
        s1 += __shfl_xor_sync(0xffffffffu, s1, 1);
        s1 += __shfl_xor_sync(0xffffffffu, s1, 2);
        l0 = l0 * c0 + s0;
        l1 = l1 * c1 + s1;
        mrun0 = mn0; mrun1 = mn1;
        #pragma unroll
        for (int nf = 0; nf < 8; nf++) {
            oacc[nf][0] *= c0; oacc[nf][1] *= c0;
            oacc[nf][2] *= c1; oacc[nf][3] *= c1;
        }

        #pragma unroll
        for (int kg = 0; kg < 4; kg++) {
            uint32_t pah[4];
            pah[0] = pack2h(sc[2 * kg][0],     sc[2 * kg][1]);
            pah[1] = pack2h(sc[2 * kg][2],     sc[2 * kg][3]);
            pah[2] = pack2h(sc[2 * kg + 1][0], sc[2 * kg + 1][1]);
            pah[3] = pack2h(sc[2 * kg + 1][2], sc[2 * kg + 1][3]);
            #pragma unroll
            for (int i = 0; i < 4; i++) {
                uint32_t bv[4];
                ldsm4t(bv, vfb + (uint32_t)(16 * kg * FSTR + i * 16) * 2);
                mma16816h(oacc[2 * i],     pah, bv);
                mma16816h(oacc[2 * i + 1], pah, bv + 2);
            }
        }
    }

    float inv0 = 1.0f / l0, inv1 = 1.0f / l1;
    size_t ob  = (size_t)(b * SS + qrow0) * ldo + h * 64;
    size_t ob8 = ob + (size_t)8 * ldo;
    #pragma unroll
    for (int nf = 0; nf < 8; nf++) {
        *(uint32_t*)(OH + ob  + nf * 8 + cq) = pack2h(oacc[nf][0] * inv0, oacc[nf][1] * inv0);
        *(uint32_t*)(OH + ob8 + nf * 8 + cq) = pack2h(oacc[nf][2] * inv1, oacc[nf][3] * inv1);
    }
}

// ---------------------------------------------------------------------------
// LayerNorm with fused fp16 output
// ---------------------------------------------------------------------------
__global__ __launch_bounds__(256)
void ln_round_kernel(const float* __restrict__ X, const float* __restrict__ gam,
                     const float* __restrict__ bet, __half* __restrict__ OH)
{
    int row = blockIdx.x;
    int t = threadIdx.x;
    int lane = t & 31, w = t >> 5;
    const float4* x4 = (const float4*)(X + (size_t)row * DD);
    float4 v = x4[t];
    float s  = v.x + v.y + v.z + v.w;
    float ss = v.x * v.x + v.y * v.y + v.z * v.z + v.w * v.w;
    #pragma unroll
    for (int o = 16; o > 0; o >>= 1) {
        s  += __shfl_xor_sync(0xffffffffu, s,  o);
        ss += __shfl_xor_sync(0xffffffffu, ss, o);
    }
    __shared__ float red[16];
    if (lane == 0) { red[w] = s; red[w + 8] = ss; }
    __syncthreads();
    float st = 0.f, sst = 0.f;
    #pragma unroll
    for (int i = 0; i < 8; i++) { st += red[i]; sst += red[i + 8]; }
    float mu   = st * (1.0f / DD);
    float var  = sst * (1.0f / DD) - mu * mu;
    float rstd = rsqrtf(var + 1e-5f);
    const float4* g4 = (const float4*)gam;
    const float4* b4 = (const float4*)bet;
    float4 gg = g4[t], bb = b4[t], o4;
    o4.x = (v.x - mu) * rstd * gg.x + bb.x;
    o4.y = (v.y - mu) * rstd * gg.y + bb.y;
    o4.z = (v.z - mu) * rstd * gg.z + bb.z;
    o4.w = (v.w - mu) * rstd * gg.w + bb.w;
    size_t off = (size_t)row * DD + t * 4;
    *(uint2*)(OH + off) = make_uint2(pack2h(o4.x, o4.y), pack2h(o4.z, o4.w));
}

// ---------------------------------------------------------------------------
// Host orchestration (single stream)
// ---------------------------------------------------------------------------
extern "C" void kernel_launch(void* const* d_in, const int* in_sizes, int n_in,
                              void* d_out, int out_size)
{
    const float* tgt      = (const float*)d_in[0];
    const float* memory   = (const float*)d_in[1];
    const float* rope_cos = (const float*)d_in[3];
    const float* rope_sin = (const float*)d_in[4];
    const float* qkv_w    = (const float*)d_in[5];
    const float* qkv_b    = (const float*)d_in[6];
    const float* out_w    = (const float*)d_in[7];
    const float* out_b    = (const float*)d_in[8];
    const float* ca_in_w  = (const float*)d_in[9];
    const float* ca_in_b  = (const float*)d_in[10];
    const float* ca_out_w = (const float*)d_in[11];
    const float* ca_out_b = (const float*)d_in[12];
    const float* ffn_w1   = (const float*)d_in[13];
    const float* ffn_b1   = (const float*)d_in[14];
    const float* ffn_w2   = (const float*)d_in[15];
    const float* ffn_b2   = (const float*)d_in[16];
    const float* ln1_g    = (const float*)d_in[17];
    const float* ln1_b    = (const float*)d_in[18];
    const float* ln2_g    = (const float*)d_in[19];
    const float* ln2_b    = (const float*)d_in[20];
    const float* ln3_g    = (const float*)d_in[21];
    const float* ln3_b    = (const float*)d_in[22];
    float* outp = (float*)d_out;

    float* S_ = nullptr;
    cudaGetSymbolAddress((void**)&S_, g_scratch);
    float*  res = S_;                         // fp32 slice 0
    __half* hb  = (__half*)(S_ + SZ);
    __half* AH   = hb;                        // 4M halves
    __half* qkvh = hb + 4194304u;             // 4096x3072
    __half* caqh = qkvh;                      // reuse
    __half* ckvh = hb + 16777216u;            // 1024x2048
    __half* FH   = hb + 18874368u;            // 4096x4096
    __half* MH   = hb + 35651584u;            // 1M halves
    __half* Wb   = hb + 36700160u;
    __half* w_qkv  = Wb;
    __half* w_out  = Wb + 3145728;
    __half* w_cain = Wb + 4194304;
    __half* w_caout= Wb + 7340032;
    __half* w_ffn1 = Wb + 8388608;
    __half* w_ffn2 = Wb + 12582912;

    static bool attr_done = false;
    if (!attr_done) {
        cudaFuncSetAttribute(mma_gemm<0, false, true, 1>, cudaFuncAttributeMaxDynamicSharedMemorySize, GSMEM_BYTES);
        cudaFuncSetAttribute(mma_gemm<0, false, true, 0>, cudaFuncAttributeMaxDynamicSharedMemorySize, GSMEM_BYTES);
        cudaFuncSetAttribute(mma_gemm<0, true, false, 0>, cudaFuncAttributeMaxDynamicSharedMemorySize, GSMEM_BYTES);
        cudaFuncSetAttribute(mma_gemm<1, false, true, 0>, cudaFuncAttributeMaxDynamicSharedMemorySize, GSMEM_BYTES);
        cudaFuncSetAttribute(fa_kernel<1>, cudaFuncAttributeMaxDynamicSharedMemorySize, FSMEM_BYTES);
        cudaFuncSetAttribute(fa_kernel<0>, cudaFuncAttributeMaxDynamicSharedMemorySize, FSMEM_BYTES);
        attr_done = true;
    }

    // ---- merged conversions: 6 weights + memory, one launch ----
    {
        ConvArgs ca;
        ca.src[0] = qkv_w;    ca.dst[0] = w_qkv;
        ca.src[1] = out_w;    ca.dst[1] = w_out;
        ca.src[2] = ca_in_w;  ca.dst[2] = w_cain;
        ca.src[3] = ca_out_w; ca.dst[3] = w_caout;
        ca.src[4] = ffn_w1;   ca.dst[4] = w_ffn1;
        ca.src[5] = ffn_w2;   ca.dst[5] = w_ffn2;
        ca.src[6] = memory;   ca.dst[6] = MH;
        int blks[7] = {1536, 512, 1536, 512, 2048, 2048, 512};
        int acc = 0;
        for (int i = 0; i < 7; i++) { ca.start[i] = acc; acc += blks[i]; }
        ca.start[7] = acc;
        conv_all<<<acc, 256>>>(ca);
    }

    // ---- self-attention block ----
    ln_round_kernel<<<ROWS, 256>>>(tgt, ln1_g, ln1_b, AH);
    mma_gemm<0, false, true, 1><<<dim3(24, 32), 256, GSMEM_BYTES>>>(
        AH, w_qkv, DD, qkv_b, nullptr, nullptr, qkvh, 3072, rope_cos, rope_sin);
    fa_kernel<1><<<dim3(SS / 128, HH, BB), 256, FSMEM_BYTES>>>(
        qkvh, 3072, qkvh + 1024, 3072, qkvh + 2048, 3072, AH, DD, SS);
    mma_gemm<0, true, false, 0><<<dim3(8, 32), 256, GSMEM_BYTES>>>(
        AH, w_out, DD, out_b, tgt, res, nullptr, DD, nullptr, nullptr);

    // ---- cross-attention block ----
    ln_round_kernel<<<ROWS, 256>>>(res, ln2_g, ln2_b, AH);
    mma_gemm<0, false, true, 0><<<dim3(8, 32), 256, GSMEM_BYTES>>>(
        AH, w_cain, DD, ca_in_b, nullptr, nullptr, caqh, DD, nullptr, nullptr);
    mma_gemm<0, false, true, 0><<<dim3(16, 8), 256, GSMEM_BYTES>>>(
        MH, w_cain + 1048576, DD, ca_in_b + 1024, nullptr, nullptr, ckvh, 2048,
        nullptr, nullptr);
    fa_kernel<0><<<dim3(SS / 128, HH, BB), 256, FSMEM_BYTES>>>(
        caqh, DD, ckvh, 2048, ckvh + 1024, 2048, AH, DD, MEMN);
    mma_gemm<0, true, false, 0><<<dim3(8, 32), 256, GSMEM_BYTES>>>(
        AH, w_caout, DD, ca_out_b, res, res, nullptr, DD, nullptr, nullptr);

    // ---- FFN block ----
    ln_round_kernel<<<ROWS, 256>>>(res, ln3_g, ln3_b, AH);
    mma_gemm<1, false, true, 0><<<dim3(32, 32), 256, GSMEM_BYTES>>>(
        AH, w_ffn1, DD, ffn_b1, nullptr, nullptr, FH, DFF, nullptr, nullptr);
    mma_gemm<0, true, false, 0><<<dim3(8, 32), 256, GSMEM_BYTES>>>(
        FH, w_ffn2, DFF, ffn_b2, res, outp, nullptr, DD, nullptr, nullptr);
}

// round 16
// speedup vs baseline: 1.9628x; 1.1484x over previous
#include <cuda_runtime.h>
#include <cuda_fp16.h>
#include <math.h>
#include <stdint.h>

// ---------------------------------------------------------------------------
// Problem constants
// ---------------------------------------------------------------------------
#define BB   4
#define SS   1024
#define DD   1024
#define HH   16
#define HD   64
#define DFF  4096
#define MEMN 256
#define ROWS (BB * SS)          // 4096

#define SZ   ((size_t)ROWS * DD)        // 4M floats per slice
__device__ float g_scratch[14 * SZ];

#define LOG2E 1.44269504088896f

// ---------------------------------------------------------------------------
// helpers
// ---------------------------------------------------------------------------
__device__ __forceinline__ uint32_t smem_u32(const void* p) {
    uint32_t a;
    asm("{ .reg .u64 t; cvta.to.shared.u64 t, %1; cvt.u32.u64 %0, t; }"
        : "=r"(a) : "l"(p));
    return a;
}
#define CPA16(dst, src) \
    asm volatile("cp.async.ca.shared.global [%0], [%1], 16;" :: "r"(dst), "l"(src))
#define CP_COMMIT() asm volatile("cp.async.commit_group;" ::: "memory")
#define CP_WAIT1()  asm volatile("cp.async.wait_group 1;"  ::: "memory")
#define CP_WAIT0()  asm volatile("cp.async.wait_group 0;"  ::: "memory")

__device__ __forceinline__ void round8h(float4 a, float4 b, uint4& hi) {
    __half2 h0 = __floats2half2_rn(a.x, a.y);
    __half2 h1 = __floats2half2_rn(a.z, a.w);
    __half2 h2 = __floats2half2_rn(b.x, b.y);
    __half2 h3 = __floats2half2_rn(b.z, b.w);
    hi.x = *(uint32_t*)&h0; hi.y = *(uint32_t*)&h1; hi.z = *(uint32_t*)&h2; hi.w = *(uint32_t*)&h3;
}
__device__ __forceinline__ uint32_t pack2h(float x, float y) {
    __half2 h = __floats2half2_rn(x, y);
    return *(uint32_t*)&h;
}
__device__ __forceinline__ float gelu_exact(float x) {
    return 0.5f * x * (1.0f + erff(x * 0.70710678118654752440f));
}
__device__ __forceinline__ void mma16816h(float* d, const uint32_t* a, const uint32_t* b) {
    asm volatile("mma.sync.aligned.m16n8k16.row.col.f32.f16.f16.f32 "
        "{%0,%1,%2,%3}, {%4,%5,%6,%7}, {%8,%9}, {%0,%1,%2,%3};"
        : "+f"(d[0]), "+f"(d[1]), "+f"(d[2]), "+f"(d[3])
        : "r"(a[0]), "r"(a[1]), "r"(a[2]), "r"(a[3]), "r"(b[0]), "r"(b[1]));
}
__device__ __forceinline__ void ldsm4(uint32_t* r, uint32_t addr) {
    asm volatile("ldmatrix.sync.aligned.m8n8.x4.shared.b16 {%0,%1,%2,%3}, [%4];"
        : "=r"(r[0]), "=r"(r[1]), "=r"(r[2]), "=r"(r[3]) : "r"(addr));
}
__device__ __forceinline__ void ldsm4t(uint32_t* r, uint32_t addr) {
    asm volatile("ldmatrix.sync.aligned.m8n8.x4.trans.shared.b16 {%0,%1,%2,%3}, [%4];"
        : "=r"(r[0]), "=r"(r[1]), "=r"(r[2]), "=r"(r[3]) : "r"(addr));
}

// ---------------------------------------------------------------------------
// Merged conversion kernel: 7 segments (6 weights + memory), one launch.
// ---------------------------------------------------------------------------
struct ConvArgs {
    const float* src[7];
    __half* dst[7];
    int start[8];
};
__global__ __launch_bounds__(256)
void conv_all(ConvArgs a) {
    int blk = blockIdx.x;
    int s = 0;
    #pragma unroll
    for (int k = 1; k < 7; k++) if (blk >= a.start[k]) s = k;
    int i = (blk - a.start[s]) * 2048 + threadIdx.x * 8;
    const float* in = a.src[s];
    float4 x = *(const float4*)(in + i);
    float4 y = *(const float4*)(in + i + 4);
    uint4 h;
    round8h(x, y, h);
    *(uint4*)(a.dst[s] + i) = h;
}

// ---------------------------------------------------------------------------
// fp16 mma.sync GEMM, BK=64 chunks, ldmatrix fragments.
// C = A@W^T + bias (+gelu) (+residual) (+rope on q/k sections when ROPEE).
// BM=BN=128, 256 threads, cp.async double-buffered, 2 CTAs/SM.
// smem row stride 72 halves (conflict-free for ldmatrix, fa-validated).
// ---------------------------------------------------------------------------
#define TSTR 72
#define GASZ (128 * TSTR)                 // halves per array (9216)
#define GBUFB (2 * GASZ * 2)              // bytes per buffer (A + W) = 36864
#define GSMEM_BYTES (2 * GBUFB)           // 73728

template<int ACT, bool HASRES, bool OHALF, int ROPEE>
__global__ __launch_bounds__(256, 2)
void mma_gemm(const __half* __restrict__ AH, const __half* __restrict__ WH,
              int K, const float* __restrict__ bias, const float* __restrict__ R,
              float* __restrict__ C, __half* __restrict__ OH, int ldc,
              const float* __restrict__ cosb, const float* __restrict__ sinb)
{
    extern __shared__ __half dsm[];
    uint32_t sb = smem_u32(dsm);

    int tid  = threadIdx.x;
    int wid  = tid >> 5, lane = tid & 31;
    int m0   = blockIdx.y * 128, n0 = blockIdx.x * 128;

    // cp.async mapping: each thread loads rows (tid>>3)+{0,32,64,96} of A and W,
    // 16B column group (tid&7)*8 halves.
    int lrow = tid >> 3;
    int lcol = (tid & 7) * 8;
    const __half* aptr = AH + (size_t)(m0 + lrow) * K + lcol;
    const __half* wptr = WH + (size_t)(n0 + lrow) * K + lcol;
    uint32_t soff = (uint32_t)(lrow * TSTR + lcol) * 2;
    const uint32_t srstep = (uint32_t)(32 * TSTR) * 2;

    int wm = (wid & 1) * 64;
    int wn = (wid >> 1) * 32;
    int r  = lane >> 2;
    int cq = (lane & 3) * 2;
    int lm  = lane & 7;
    int grp = lane >> 3;
    uint32_t aoff = (uint32_t)((((grp & 1) * 8 + lm) * TSTR + (grp >> 1) * 8)) * 2;
    uint32_t boff = (uint32_t)((((grp >> 1) * 8 + lm) * TSTR + (grp & 1) * 8)) * 2;

    float acc[4][4][4];
    #pragma unroll
    for (int mt = 0; mt < 4; mt++)
        #pragma unroll
        for (int nt = 0; nt < 4; nt++)
            #pragma unroll
            for (int i = 0; i < 4; i++) acc[mt][nt][i] = 0.f;

    // chunk 0 into buffer 0
    #pragma unroll
    for (int s = 0; s < 4; s++) {
        CPA16(sb + soff + s * srstep,            aptr + (size_t)(32 * s) * K);
        CPA16(sb + GASZ * 2 + soff + s * srstep, wptr + (size_t)(32 * s) * K);
    }
    CP_COMMIT();

    int NC = K >> 6;
    for (int c = 0; c < NC; ++c) {
        if (c + 1 < NC) {
            uint32_t bfo = (uint32_t)(((c + 1) & 1) * GBUFB);
            const __half* an = aptr + (c + 1) * 64;
            const __half* wn2 = wptr + (c + 1) * 64;
            #pragma unroll
            for (int s = 0; s < 4; s++) {
                CPA16(sb + bfo + soff + s * srstep,            an + (size_t)(32 * s) * K);
                CPA16(sb + bfo + GASZ * 2 + soff + s * srstep, wn2 + (size_t)(32 * s) * K);
            }
            CP_COMMIT();
            CP_WAIT1();
        } else {
            CP_WAIT0();
        }
        __syncthreads();

        {
            uint32_t ab = sb + (c & 1) * GBUFB;
            uint32_t bb = ab + GASZ * 2;
            #pragma unroll
            for (int kh = 0; kh < 4; kh++) {
                uint32_t kofs = (uint32_t)(kh * 16) * 2;
                uint32_t ah[4][4], bh[4][2];
                #pragma unroll
                for (int mt = 0; mt < 4; mt++)
                    ldsm4(ah[mt], ab + aoff + kofs +
                          (uint32_t)((wm + mt * 16) * TSTR) * 2);
                #pragma unroll
                for (int ntp = 0; ntp < 2; ntp++) {
                    uint32_t bregs[4];
                    ldsm4(bregs, bb + boff + kofs +
                          (uint32_t)((wn + ntp * 16) * TSTR) * 2);
                    bh[2 * ntp][0]     = bregs[0];
                    bh[2 * ntp][1]     = bregs[1];
                    bh[2 * ntp + 1][0] = bregs[2];
                    bh[2 * ntp + 1][1] = bregs[3];
                }
                #pragma unroll
                for (int mt = 0; mt < 4; mt++)
                    #pragma unroll
                    for (int nt = 0; nt < 4; nt++)
                        mma16816h(acc[mt][nt], ah[mt], bh[nt]);
            }
        }
        __syncthreads();
    }

    #pragma unroll
    for (int mt = 0; mt < 4; mt++) {
        int row0 = m0 + wm + mt * 16 + r;
        #pragma unroll
        for (int nt = 0; nt < 4; nt++) {
            int coln = n0 + wn + nt * 8 + cq;
            float2 bv = *(const float2*)(bias + coln);
            float v0 = acc[mt][nt][0] + bv.x;
            float v1 = acc[mt][nt][1] + bv.y;
            float v2 = acc[mt][nt][2] + bv.x;
            float v3 = acc[mt][nt][3] + bv.y;
            if (ACT == 1) {
                v0 = gelu_exact(v0); v1 = gelu_exact(v1);
                v2 = gelu_exact(v2); v3 = gelu_exact(v3);
            }
            if (ROPEE) {
                if ((coln >> 10) < 2) {
                    int i  = (coln & 63) >> 1;
                    int s0 = row0 & (SS - 1);
                    float c0r = cosb[s0 * 32 + i],       s0r = sinb[s0 * 32 + i];
                    float c8r = cosb[(s0 + 8) * 32 + i], s8r = sinb[(s0 + 8) * 32 + i];
                    float t0 = v0 * c0r - v1 * s0r, t1 = v0 * s0r + v1 * c0r;
                    float t2 = v2 * c8r - v3 * s8r, t3 = v2 * s8r + v3 * c8r;
                    v0 = t0; v1 = t1; v2 = t2; v3 = t3;
                }
            }
            if (HASRES) {
                float2 r0 = *(const float2*)(R + (size_t)row0 * ldc + coln);
                float2 r1 = *(const float2*)(R + (size_t)(row0 + 8) * ldc + coln);
                v0 += r0.x; v1 += r0.y; v2 += r1.x; v3 += r1.y;
            }
            if (OHALF) {
                *(uint32_t*)(OH + (size_t)row0 * ldc + coln)       = pack2h(v0, v1);
                *(uint32_t*)(OH + (size_t)(row0 + 8) * ldc + coln) = pack2h(v2, v3);
            } else {
                *(float2*)(C + (size_t)row0 * ldc + coln)       = make_float2(v0, v1);
                *(float2*)(C + (size_t)(row0 + 8) * ldc + coln) = make_float2(v2, v3);
            }
        }
    }
}

// ---------------------------------------------------------------------------
// fp16 flash attention (unchanged from R15 passing kernel)
// ---------------------------------------------------------------------------
#define FSTR 72
#define KTILEH (64 * FSTR)
#define FBUFH  (2 * KTILEH)
#define FBUFB  (FBUFH * 2)
#define FSMEM_BYTES (2 * FBUFB)     // 36864

template<int CAUSAL>
__global__ __launch_bounds__(256, 2)
void fa_kernel(const __half* __restrict__ Q, int ldq,
               const __half* __restrict__ Kp, int ldk,
               const __half* __restrict__ Vp, int ldv,
               __half* __restrict__ OH, int ldo, int kvlen)
{
    extern __shared__ __half fsm[];
    uint32_t sb = smem_u32(fsm);

    int tid = threadIdx.x;
    int wid = tid >> 5, lane = tid & 31;
    int r   = lane >> 2;
    int cq  = (lane & 3) * 2;
    int b = blockIdx.z, h = blockIdx.y;
    int q0 = blockIdx.x * 128;
    int qrow0 = q0 + wid * 16 + r;
    int wmin  = q0 + wid * 16;
    int wmax  = wmin + 15;

    int lm  = lane & 7;
    int grp = lane >> 3;
    uint32_t kfrag0 = (uint32_t)((((grp >> 1) * 8 + lm) * FSTR + 8 * (grp & 1))) * 2;
    uint32_t vfrag0 = (uint32_t)(((8 * (grp & 1) + lm) * FSTR + (grp >> 1) * 8)) * 2;

    int kkey = tid >> 2, kdg = (tid & 3) * 16;
    const __half* ksrc = Kp + (size_t)(b * kvlen + kkey) * ldk + h * 64 + kdg;
    const __half* vsrc = Vp + (size_t)(b * kvlen + kkey) * ldv + h * 64 + kdg;
    uint32_t kdst = sb + (uint32_t)(kkey * FSTR + kdg) * 2;
    uint32_t vdst = kdst + KTILEH * 2;

    uint32_t qh[4][4];
    {
        const float qs = 0.125f * LOG2E;
        const __half* qb  = Q + (size_t)(b * SS + qrow0) * ldq + h * 64;
        const __half* qb8 = qb + (size_t)8 * ldq;
        #pragma unroll
        for (int ks = 0; ks < 4; ks++) {
            float2 f0 = __half22float2(*(const __half2*)(qb  + 16 * ks + cq));
            float2 f1 = __half22float2(*(const __half2*)(qb8 + 16 * ks + cq));
            float2 f2 = __half22float2(*(const __half2*)(qb  + 16 * ks + cq + 8));
            float2 f3 = __half22float2(*(const __half2*)(qb8 + 16 * ks + cq + 8));
            qh[ks][0] = pack2h(f0.x * qs, f0.y * qs);
            qh[ks][1] = pack2h(f1.x * qs, f1.y * qs);
            qh[ks][2] = pack2h(f2.x * qs, f2.y * qs);
            qh[ks][3] = pack2h(f3.x * qs, f3.y * qs);
        }
    }

    float oacc[8][4];
    #pragma unroll
    for (int nf = 0; nf < 8; nf++)
        #pragma unroll
        for (int i = 0; i < 4; i++) oacc[nf][i] = 0.f;
    float mrun0 = -INFINITY, mrun1 = -INFINITY, l0 = 0.f, l1 = 0.f;

    int ntiles = CAUSAL ? ((q0 >> 6) + 2) : (kvlen >> 6);

    {
        CPA16(kdst,      ksrc);
        CPA16(kdst + 16, ksrc + 8);
        CPA16(vdst,      vsrc);
        CPA16(vdst + 16, vsrc + 8);
        CP_COMMIT();
    }

    for (int tile = 0; tile < ntiles; tile++) {
        uint32_t bo = (uint32_t)(tile & 1) * FBUFB;
        __syncthreads();
        if (tile + 1 < ntiles) {
            uint32_t nbo = (uint32_t)((tile + 1) & 1) * FBUFB;
            size_t go = (size_t)(tile + 1) * 64 * ldk;
            size_t gv = (size_t)(tile + 1) * 64 * ldv;
            CPA16(kdst + nbo,      ksrc + go);
            CPA16(kdst + nbo + 16, ksrc + go + 8);
            CPA16(vdst + nbo,      vsrc + gv);
            CPA16(vdst + nbo + 16, vsrc + gv + 8);
            CP_COMMIT();
            CP_WAIT1();
        } else {
            CP_WAIT0();
        }
        __syncthreads();

        int t0 = tile * 64;
        bool active = !CAUSAL || (t0 <= wmax);
        if (!active) continue;

        uint32_t kfb = sb + bo + kfrag0;
        uint32_t vfb = sb + bo + KTILEH * 2 + vfrag0;

        float sc[8][4];
        #pragma unroll
        for (int nf = 0; nf < 8; nf++)
            #pragma unroll
            for (int i = 0; i < 4; i++) sc[nf][i] = 0.f;

        #pragma unroll
        for (int ks = 0; ks < 4; ks++) {
            #pragma unroll
            for (int i = 0; i < 4; i++) {
                uint32_t bh[4];
                ldsm4(bh, kfb + (uint32_t)(i * 16 * FSTR + 16 * ks) * 2);
                mma16816h(sc[2 * i],     qh[ks], bh);
                mma16816h(sc[2 * i + 1], qh[ks], bh + 2);
            }
        }

        if (CAUSAL && (t0 + 63 > wmin)) {
            #pragma unroll
            for (int nf = 0; nf < 8; nf++) {
                int jb = t0 + nf * 8 + cq;
                if (jb     > qrow0)     sc[nf][0] = -INFINITY;
                if (jb + 1 > qrow0)     sc[nf][1] = -INFINITY;
                if (jb     > qrow0 + 8) sc[nf][2] = -INFINITY;
                if (jb + 1 > qrow0 + 8) sc[nf][3] = -INFINITY;
            }
        }

        float mx0 = -INFINITY, mx1 = -INFINITY;
        #pragma unroll
        for (int nf = 0; nf < 8; nf++) {
            mx0 = fmaxf(mx0, fmaxf(sc[nf][0], sc[nf][1]));
            mx1 = fmaxf(mx1, fmaxf(sc[nf][2], sc[nf][3]));
        }
        mx0 = fmaxf(mx0, __shfl_xor_sync(0xffffffffu, mx0, 1));
        mx0 = fmaxf(mx0, __shfl_xor_sync(0xffffffffu, mx0, 2));
        mx1 = fmaxf(mx1, __shfl_xor_sync(0xffffffffu, mx1, 1));
        mx1 = fmaxf(mx1, __shfl_xor_sync(0xffffffffu, mx1, 2));
        float mn0 = fmaxf(mrun0, mx0), mn1 = fmaxf(mrun1, mx1);
        float c0 = exp2f(mrun0 - mn0), c1 = exp2f(mrun1 - mn1);
        float s0 = 0.f, s1 = 0.f;
        #pragma unroll
        for (int nf = 0; nf < 8; nf++) {
            sc[nf][0] = exp2f(sc[nf][0] - mn0);
            sc[nf][1] = exp2f(sc[nf][1] - mn0);
            sc[nf][2] = exp2f(sc[nf][2] - mn1);
            sc[nf][3] = exp2f(sc[nf][3] - mn1);
            s0 += sc[nf][0] + sc[nf][1];
            s1 += sc[nf][2] + sc[nf][3];
        }
        s0 += __shfl_xor_sync(0xffffffffu, s0, 1);
        s0 += __shfl_xor_sync(0xffffffffu, s0, 2);
        s1 += __shfl_xor_sync(0xffffffffu, s1, 1);
        s1 += __shfl_xor_sync(0xffffffffu, s1, 2);
        l0 = l0 * c0 + s0;
        l1 = l1 * c1 + s1;
        mrun0 = mn0; mrun1 = mn1;
        #pragma unroll
        for (int nf = 0; nf < 8; nf++) {
            oacc[nf][0] *= c0; oacc[nf][1] *= c0;
            oacc[nf][2] *= c1; oacc[nf][3] *= c1;
        }

        #pragma unroll
        for (int kg = 0; kg < 4; kg++) {
            uint32_t pah[4];
            pah[0] = pack2h(sc[2 * kg][0],     sc[2 * kg][1]);
            pah[1] = pack2h(sc[2 * kg][2],     sc[2 * kg][3]);
            pah[2] = pack2h(sc[2 * kg + 1][0], sc[2 * kg + 1][1]);
            pah[3] = pack2h(sc[2 * kg + 1][2], sc[2 * kg + 1][3]);
            #pragma unroll
            for (int i = 0; i < 4; i++) {
                uint32_t bv[4];
                ldsm4t(bv, vfb + (uint32_t)(16 * kg * FSTR + i * 16) * 2);
                mma16816h(oacc[2 * i],     pah, bv);
                mma16816h(oacc[2 * i + 1], pah, bv + 2);
            }
        }
    }

    float inv0 = 1.0f / l0, inv1 = 1.0f / l1;
    size_t ob  = (size_t)(b * SS + qrow0) * ldo + h * 64;
    size_t ob8 = ob + (size_t)8 * ldo;
    #pragma unroll
    for (int nf = 0; nf < 8; nf++) {
        *(uint32_t*)(OH + ob  + nf * 8 + cq) = pack2h(oacc[nf][0] * inv0, oacc[nf][1] * inv0);
        *(uint32_t*)(OH + ob8 + nf * 8 + cq) = pack2h(oacc[nf][2] * inv1, oacc[nf][3] * inv1);
    }
}

// ---------------------------------------------------------------------------
// LayerNorm with fused fp16 output
// ---------------------------------------------------------------------------
__global__ __launch_bounds__(256)
void ln_round_kernel(const float* __restrict__ X, const float* __restrict__ gam,
                     const float* __restrict__ bet, __half* __restrict__ OH)
{
    int row = blockIdx.x;
    int t = threadIdx.x;
    int lane = t & 31, w = t >> 5;
    const float4* x4 = (const float4*)(X + (size_t)row * DD);
    float4 v = x4[t];
    float s  = v.x + v.y + v.z + v.w;
    float ss = v.x * v.x + v.y * v.y + v.z * v.z + v.w * v.w;
    #pragma unroll
    for (int o = 16; o > 0; o >>= 1) {
        s  += __shfl_xor_sync(0xffffffffu, s,  o);
        ss += __shfl_xor_sync(0xffffffffu, ss, o);
    }
    __shared__ float red[16];
    if (lane == 0) { red[w] = s; red[w + 8] = ss; }
    __syncthreads();
    float st = 0.f, sst = 0.f;
    #pragma unroll
    for (int i = 0; i < 8; i++) { st += red[i]; sst += red[i + 8]; }
    float mu   = st * (1.0f / DD);
    float var  = sst * (1.0f / DD) - mu * mu;
    float rstd = rsqrtf(var + 1e-5f);
    const float4* g4 = (const float4*)gam;
    const float4* b4 = (const float4*)bet;
    float4 gg = g4[t], bb = b4[t], o4;
    o4.x = (v.x - mu) * rstd * gg.x + bb.x;
    o4.y = (v.y - mu) * rstd * gg.y + bb.y;
    o4.z = (v.z - mu) * rstd * gg.z + bb.z;
    o4.w = (v.w - mu) * rstd * gg.w + bb.w;
    size_t off = (size_t)row * DD + t * 4;
    *(uint2*)(OH + off) = make_uint2(pack2h(o4.x, o4.y), pack2h(o4.z, o4.w));
}

// ---------------------------------------------------------------------------
// Host orchestration (single stream)
// ---------------------------------------------------------------------------
extern "C" void kernel_launch(void* const* d_in, const int* in_sizes, int n_in,
                              void* d_out, int out_size)
{
    const float* tgt      = (const float*)d_in[0];
    const float* memory   = (const float*)d_in[1];
    const float* rope_cos = (const float*)d_in[3];
    const float* rope_sin = (const float*)d_in[4];
    const float* qkv_w    = (const float*)d_in[5];
    const float* qkv_b    = (const float*)d_in[6];
    const float* out_w    = (const float*)d_in[7];
    const float* out_b    = (const float*)d_in[8];
    const float* ca_in_w  = (const float*)d_in[9];
    const float* ca_in_b  = (const float*)d_in[10];
    const float* ca_out_w = (const float*)d_in[11];
    const float* ca_out_b = (const float*)d_in[12];
    const float* ffn_w1   = (const float*)d_in[13];
    const float* ffn_b1   = (const float*)d_in[14];
    const float* ffn_w2   = (const float*)d_in[15];
    const float* ffn_b2   = (const float*)d_in[16];
    const float* ln1_g    = (const float*)d_in[17];
    const float* ln1_b    = (const float*)d_in[18];
    const float* ln2_g    = (const float*)d_in[19];
    const float* ln2_b    = (const float*)d_in[20];
    const float* ln3_g    = (const float*)d_in[21];
    const float* ln3_b    = (const float*)d_in[22];
    float* outp = (float*)d_out;

    float* S_ = nullptr;
    cudaGetSymbolAddress((void**)&S_, g_scratch);
    float*  res = S_;                         // fp32 slice 0
    __half* hb  = (__half*)(S_ + SZ);
    __half* AH   = hb;                        // 4M halves
    __half* qkvh = hb + 4194304u;             // 4096x3072
    __half* caqh = qkvh;                      // reuse
    __half* ckvh = hb + 16777216u;            // 1024x2048
    __half* FH   = hb + 18874368u;            // 4096x4096
    __half* MH   = hb + 35651584u;            // 1M halves
    __half* Wb   = hb + 36700160u;
    __half* w_qkv  = Wb;
    __half* w_out  = Wb + 3145728;
    __half* w_cain = Wb + 4194304;
    __half* w_caout= Wb + 7340032;
    __half* w_ffn1 = Wb + 8388608;
    __half* w_ffn2 = Wb + 12582912;

    static bool attr_done = false;
    if (!attr_done) {
        cudaFuncSetAttribute(mma_gemm<0, false, true, 1>, cudaFuncAttributeMaxDynamicSharedMemorySize, GSMEM_BYTES);
        cudaFuncSetAttribute(mma_gemm<0, false, true, 0>, cudaFuncAttributeMaxDynamicSharedMemorySize, GSMEM_BYTES);
        cudaFuncSetAttribute(mma_gemm<0, true, false, 0>, cudaFuncAttributeMaxDynamicSharedMemorySize, GSMEM_BYTES);
        cudaFuncSetAttribute(mma_gemm<1, false, true, 0>, cudaFuncAttributeMaxDynamicSharedMemorySize, GSMEM_BYTES);
        cudaFuncSetAttribute(fa_kernel<1>, cudaFuncAttributeMaxDynamicSharedMemorySize, FSMEM_BYTES);
        cudaFuncSetAttribute(fa_kernel<0>, cudaFuncAttributeMaxDynamicSharedMemorySize, FSMEM_BYTES);
        attr_done = true;
    }

    // ---- merged conversions: 6 weights + memory, one launch ----
    {
        ConvArgs ca;
        ca.src[0] = qkv_w;    ca.dst[0] = w_qkv;
        ca.src[1] = out_w;    ca.dst[1] = w_out;
        ca.src[2] = ca_in_w;  ca.dst[2] = w_cain;
        ca.src[3] = ca_out_w; ca.dst[3] = w_caout;
        ca.src[4] = ffn_w1;   ca.dst[4] = w_ffn1;
        ca.src[5] = ffn_w2;   ca.dst[5] = w_ffn2;
        ca.src[6] = memory;   ca.dst[6] = MH;
        int blks[7] = {1536, 512, 1536, 512, 2048, 2048, 512};
        int acc = 0;
        for (int i = 0; i < 7; i++) { ca.start[i] = acc; acc += blks[i]; }
        ca.start[7] = acc;
        conv_all<<<acc, 256>>>(ca);
    }

    // ---- self-attention block ----
    ln_round_kernel<<<ROWS, 256>>>(tgt, ln1_g, ln1_b, AH);
    mma_gemm<0, false, true, 1><<<dim3(24, 32), 256, GSMEM_BYTES>>>(
        AH, w_qkv, DD, qkv_b, nullptr, nullptr, qkvh, 3072, rope_cos, rope_sin);
    fa_kernel<1><<<dim3(SS / 128, HH, BB), 256, FSMEM_BYTES>>>(
        qkvh, 3072, qkvh + 1024, 3072, qkvh + 2048, 3072, AH, DD, SS);
    mma_gemm<0, true, false, 0><<<dim3(8, 32), 256, GSMEM_BYTES>>>(
        AH, w_out, DD, out_b, tgt, res, nullptr, DD, nullptr, nullptr);

    // ---- cross-attention block ----
    ln_round_kernel<<<ROWS, 256>>>(res, ln2_g, ln2_b, AH);
    mma_gemm<0, false, true, 0><<<dim3(8, 32), 256, GSMEM_BYTES>>>(
        AH, w_cain, DD, ca_in_b, nullptr, nullptr, caqh, DD, nullptr, nullptr);
    mma_gemm<0, false, true, 0><<<dim3(16, 8), 256, GSMEM_BYTES>>>(
        MH, w_cain + 1048576, DD, ca_in_b + 1024, nullptr, nullptr, ckvh, 2048,
        nullptr, nullptr);
    fa_kernel<0><<<dim3(SS / 128, HH, BB), 256, FSMEM_BYTES>>>(
        caqh, DD, ckvh, 2048, ckvh + 1024, 2048, AH, DD, MEMN);
    mma_gemm<0, true, false, 0><<<dim3(8, 32), 256, GSMEM_BYTES>>>(
        AH, w_caout, DD, ca_out_b, res, res, nullptr, DD, nullptr, nullptr);

    // ---- FFN block ----
    ln_round_kernel<<<ROWS, 256>>>(res, ln3_g, ln3_b, AH);
    mma_gemm<1, false, true, 0><<<dim3(32, 32), 256, GSMEM_BYTES>>>(
        AH, w_ffn1, DD, ffn_b1, nullptr, nullptr, FH, DFF, nullptr, nullptr);
    mma_gemm<0, true, false, 0><<<dim3(8, 32), 256, GSMEM_BYTES>>>(
        FH, w_ffn2, DFF, ffn_b2, res, outp, nullptr, DD, nullptr, nullptr);
}